// round 1
// baseline (speedup 1.0000x reference)
#include <cuda_runtime.h>
#include <math.h>
#include <stdint.h>

#define NNODES 50000
#define NEDGES 800000
#define ETOT   (NEDGES + NNODES)
#define NLBL   100000
#define FIN    128
#define HH     4
#define CC     64
#define DD     256

// ---------------- scratch (device globals; no allocation allowed) ----------
__device__ int   g_flag64_e;
__device__ int   g_flag64_l;
__device__ int   g_rowptr[NNODES + 1];
__device__ int   g_fill[NNODES];
__device__ int   g_csr_src[ETOT];
__device__ int   g_esrc[ETOT];
__device__ int   g_edst[ETOT];
__device__ int   g_lu[NLBL];
__device__ int   g_lv[NLBL];
__device__ float g_hbuf[(size_t)NNODES * DD];   // GEMM output / agg input
__device__ float g_zbuf[(size_t)NNODES * DD];   // agg output / next GEMM input
__device__ float g_als[NNODES * HH];
__device__ float g_ald[NNODES * HH];
__device__ float g_alpha[(size_t)ETOT * HH];    // CSR-ordered attention weights
__device__ float g_hid[(size_t)NLBL * CC];

// ---------------- dtype detection (int64 vs int32 edge arrays) -------------
__device__ __forceinline__ int check_is_i64(const long long* q) {
    int ok = 1;
#pragma unroll
    for (int i = 0; i < 8; i++) {
        long long v = q[i];
        if (v < 0 || v >= NNODES) ok = 0;
    }
    return ok;
}

__global__ void detect_dtype(const void* ei, const void* eli) {
    g_flag64_e = check_is_i64((const long long*)ei);
    g_flag64_l = check_is_i64((const long long*)eli);
}

// ---------------- edge conversion + self loops ------------------------------
__global__ void build_edges(const void* ei) {
    int i = blockIdx.x * blockDim.x + threadIdx.x;
    if (i >= ETOT) return;
    int s, d;
    if (i < NEDGES) {
        if (g_flag64_e) {
            const long long* q = (const long long*)ei;
            s = (int)q[i]; d = (int)q[NEDGES + i];
        } else {
            const int* q = (const int*)ei;
            s = q[i]; d = q[NEDGES + i];
        }
    } else {
        s = i - NEDGES; d = s;   // self loop
    }
    g_esrc[i] = s; g_edst[i] = d;
}

__global__ void build_labels(const void* eli) {
    int i = blockIdx.x * blockDim.x + threadIdx.x;
    if (i >= NLBL) return;
    if (g_flag64_l) {
        const long long* q = (const long long*)eli;
        g_lu[i] = (int)q[i]; g_lv[i] = (int)q[NLBL + i];
    } else {
        const int* q = (const int*)eli;
        g_lu[i] = q[i]; g_lv[i] = q[NLBL + i];
    }
}

// ---------------- CSR build -------------------------------------------------
__global__ void zero_fill_k() {
    int i = blockIdx.x * blockDim.x + threadIdx.x;
    if (i < NNODES) g_fill[i] = 0;
}

__global__ void hist_k() {
    int i = blockIdx.x * blockDim.x + threadIdx.x;
    if (i < ETOT) atomicAdd(&g_fill[g_edst[i]], 1);
}

// single-block exclusive scan: g_fill (deg) -> g_rowptr, g_fill = exclusive
__global__ void scan_k() {
    __shared__ int sh[1024];
    __shared__ int carry;
    int t = threadIdx.x;
    if (t == 0) { carry = 0; g_rowptr[0] = 0; }
    __syncthreads();
    for (int base = 0; base < NNODES; base += 1024) {
        int i = base + t;
        int v = (i < NNODES) ? g_fill[i] : 0;
        sh[t] = v;
        __syncthreads();
        for (int off = 1; off < 1024; off <<= 1) {
            int add = (t >= off) ? sh[t - off] : 0;
            __syncthreads();
            sh[t] += add;
            __syncthreads();
        }
        int incl = sh[t];
        int c = carry;
        __syncthreads();
        if (i < NNODES) {
            g_rowptr[i + 1] = c + incl;
            g_fill[i] = c + incl - v;
        }
        if (t == 1023) carry = c + incl;
        __syncthreads();
    }
}

__global__ void scatter_k() {
    int i = blockIdx.x * blockDim.x + threadIdx.x;
    if (i >= ETOT) return;
    int pos = atomicAdd(&g_fill[g_edst[i]], 1);
    g_csr_src[pos] = g_esrc[i];
}

// ---------------- tiled fp32 GEMM: C[M,Nc] = A[M,K] @ B[K,Nc] ---------------
// GATHER: logical A row g = concat(z[lu[g]], z[lv[g]]), K must be 512, A = z
// BIASRELU: C = relu(C + bias[col])
template <bool GATHER, bool BIASRELU>
__global__ void gemm64(const float* __restrict__ A, const float* __restrict__ B,
                       float* __restrict__ C, int M, int K, int Nc,
                       const int* __restrict__ lu, const int* __restrict__ lv,
                       const float* __restrict__ bias) {
    __shared__ __align__(16) float As[16][68];
    __shared__ __align__(16) float Bs[16][64];
    int tid = threadIdx.x;
    int tx = tid & 15, ty = tid >> 4;
    int rowBase = blockIdx.y * 64, colBase = blockIdx.x * 64;

    int arow = tid >> 2;           // 0..63
    int ac0  = (tid & 3) * 4;      // 0,4,8,12
    int brow = tid >> 4;           // 0..15
    int bc0  = (tid & 15) * 4;

    int g = rowBase + arow;
    float acc[4][4] = {};

    for (int k0 = 0; k0 < K; k0 += 16) {
        float4 av = make_float4(0.f, 0.f, 0.f, 0.f);
        if (g < M) {
            const float* Ap;
            if (GATHER) {
                int idx = (k0 < 256) ? lu[g] : lv[g];
                int kk0 = (k0 < 256) ? k0 : (k0 - 256);
                Ap = A + (size_t)idx * 256 + kk0;
            } else {
                Ap = A + (size_t)g * K + k0;
            }
            av = *(const float4*)(Ap + ac0);
        }
        float4 bv = *(const float4*)(B + (size_t)(k0 + brow) * Nc + colBase + bc0);

        As[ac0 + 0][arow] = av.x;
        As[ac0 + 1][arow] = av.y;
        As[ac0 + 2][arow] = av.z;
        As[ac0 + 3][arow] = av.w;
        *(float4*)&Bs[brow][bc0] = bv;
        __syncthreads();

#pragma unroll
        for (int kk = 0; kk < 16; kk++) {
            float4 a = *(const float4*)&As[kk][ty * 4];
            float4 b = *(const float4*)&Bs[kk][tx * 4];
            float av_[4] = {a.x, a.y, a.z, a.w};
            float bv_[4] = {b.x, b.y, b.z, b.w};
#pragma unroll
            for (int i = 0; i < 4; i++)
#pragma unroll
                for (int j = 0; j < 4; j++)
                    acc[i][j] = fmaf(av_[i], bv_[j], acc[i][j]);
        }
        __syncthreads();
    }

#pragma unroll
    for (int i = 0; i < 4; i++) {
        int r = rowBase + ty * 4 + i;
        if (r < M) {
            float4 v = make_float4(acc[i][0], acc[i][1], acc[i][2], acc[i][3]);
            if (BIASRELU) {
                int c = colBase + tx * 4;
                v.x = fmaxf(v.x + bias[c + 0], 0.f);
                v.y = fmaxf(v.y + bias[c + 1], 0.f);
                v.z = fmaxf(v.z + bias[c + 2], 0.f);
                v.w = fmaxf(v.w + bias[c + 3], 0.f);
            }
            *(float4*)(C + (size_t)r * Nc + colBase + tx * 4) = v;
        }
    }
}

// ---------------- attention logits: al[n][h] = <h[n,h,:], a[h,:]> -----------
__global__ void attn_logits(const float* __restrict__ a_src,
                            const float* __restrict__ a_dst) {
    int n = blockIdx.x;
    int w = threadIdx.x >> 5, lane = threadIdx.x & 31;
    const float* hr = g_hbuf + (size_t)n * 256 + w * 64;
    float x0 = hr[lane], x1 = hr[lane + 32];
    float s = x0 * a_src[w * 64 + lane] + x1 * a_src[w * 64 + lane + 32];
    float d = x0 * a_dst[w * 64 + lane] + x1 * a_dst[w * 64 + lane + 32];
#pragma unroll
    for (int o = 16; o; o >>= 1) {
        s += __shfl_xor_sync(0xffffffffu, s, o);
        d += __shfl_xor_sync(0xffffffffu, d, o);
    }
    if (!lane) { g_als[n * 4 + w] = s; g_ald[n * 4 + w] = d; }
}

// ---------------- per-node softmax over incoming edges (warp/node) ----------
__global__ void attn_softmax_k() {
    int node = (blockIdx.x * blockDim.x + threadIdx.x) >> 5;
    int lane = threadIdx.x & 31;
    if (node >= NNODES) return;
    int beg = g_rowptr[node], end = g_rowptr[node + 1];

    float4 adv = *(const float4*)&g_ald[node * 4];
    float ad[4] = {adv.x, adv.y, adv.z, adv.w};

    float mx[4] = {-INFINITY, -INFINITY, -INFINITY, -INFINITY};
    for (int k = beg + lane; k < end; k += 32) {
        int s = g_csr_src[k];
        float4 av = *(const float4*)&g_als[s * 4];
        float e[4] = {av.x + ad[0], av.y + ad[1], av.z + ad[2], av.w + ad[3]};
#pragma unroll
        for (int h = 0; h < 4; h++) {
            float v = e[h] > 0.f ? e[h] : 0.2f * e[h];
            mx[h] = fmaxf(mx[h], v);
        }
    }
#pragma unroll
    for (int h = 0; h < 4; h++)
#pragma unroll
        for (int o = 16; o; o >>= 1)
            mx[h] = fmaxf(mx[h], __shfl_xor_sync(0xffffffffu, mx[h], o));

    float sm[4] = {0.f, 0.f, 0.f, 0.f};
    for (int k = beg + lane; k < end; k += 32) {
        int s = g_csr_src[k];
        float4 av = *(const float4*)&g_als[s * 4];
        float e[4] = {av.x + ad[0], av.y + ad[1], av.z + ad[2], av.w + ad[3]};
        float p[4];
#pragma unroll
        for (int h = 0; h < 4; h++) {
            float v = e[h] > 0.f ? e[h] : 0.2f * e[h];
            p[h] = __expf(v - mx[h]);
            sm[h] += p[h];
        }
        *(float4*)&g_alpha[(size_t)k * 4] = make_float4(p[0], p[1], p[2], p[3]);
    }
#pragma unroll
    for (int h = 0; h < 4; h++) {
#pragma unroll
        for (int o = 16; o; o >>= 1)
            sm[h] += __shfl_xor_sync(0xffffffffu, sm[h], o);
        sm[h] = 1.f / sm[h];
    }
    for (int k = beg + lane; k < end; k += 32) {
        float4 p = *(const float4*)&g_alpha[(size_t)k * 4];
        p.x *= sm[0]; p.y *= sm[1]; p.z *= sm[2]; p.w *= sm[3];
        *(float4*)&g_alpha[(size_t)k * 4] = p;
    }
}

// ---------------- pull aggregation + bias + ELU -----------------------------
__global__ void aggregate_k(const float* __restrict__ bias) {
    int n = blockIdx.x, t = threadIdx.x, hh = t >> 6;
    int beg = g_rowptr[n], end = g_rowptr[n + 1];
    float acc = 0.f;
#pragma unroll 4
    for (int k = beg; k < end; k++) {
        int s = g_csr_src[k];                       // broadcast
        float w = g_alpha[(size_t)k * 4 + hh];      // 4 distinct addrs
        acc = fmaf(w, g_hbuf[(size_t)s * 256 + t], acc);
    }
    float v = acc + bias[t];
    g_zbuf[(size_t)n * 256 + t] = v > 0.f ? v : (__expf(v) - 1.f);
}

// ---------------- final score: out[e] = <hid[e,:], Ws2> + bs2 ---------------
__global__ void final_score_k(const float* __restrict__ hid,
                              const float* __restrict__ Ws2,
                              const float* __restrict__ bs2,
                              float* __restrict__ out) {
    int e = (blockIdx.x * blockDim.x + threadIdx.x) >> 5;
    int lane = threadIdx.x & 31;
    if (e >= NLBL) return;
    const float* hp = hid + (size_t)e * 64;
    float s = hp[lane] * Ws2[lane] + hp[lane + 32] * Ws2[lane + 32];
#pragma unroll
    for (int o = 16; o; o >>= 1) s += __shfl_xor_sync(0xffffffffu, s, o);
    if (!lane) out[e] = s + bs2[0];
}

// ---------------- launcher --------------------------------------------------
extern "C" void kernel_launch(void* const* d_in, const int* in_sizes, int n_in,
                              void* d_out, int out_size) {
    const float* x   = (const float*)d_in[0];
    const void*  ei  = d_in[1];
    const void*  eli = d_in[2];
    const float* W1  = (const float*)d_in[3];
    const float* as1 = (const float*)d_in[4];
    const float* ad1 = (const float*)d_in[5];
    const float* b1  = (const float*)d_in[6];
    const float* W2  = (const float*)d_in[7];
    const float* as2 = (const float*)d_in[8];
    const float* ad2 = (const float*)d_in[9];
    const float* b2  = (const float*)d_in[10];
    const float* Ws1 = (const float*)d_in[11];
    const float* bs1 = (const float*)d_in[12];
    const float* Ws2 = (const float*)d_in[13];
    const float* bs2 = (const float*)d_in[14];
    float* out = (float*)d_out;

    float *hptr, *zptr, *hidptr;
    int *luptr, *lvptr;
    cudaGetSymbolAddress((void**)&hptr, g_hbuf);
    cudaGetSymbolAddress((void**)&zptr, g_zbuf);
    cudaGetSymbolAddress((void**)&hidptr, g_hid);
    cudaGetSymbolAddress((void**)&luptr, g_lu);
    cudaGetSymbolAddress((void**)&lvptr, g_lv);

    // graph prep (same every call; must be redone per launch)
    detect_dtype<<<1, 1>>>(ei, eli);
    build_edges<<<(ETOT + 255) / 256, 256>>>(ei);
    build_labels<<<(NLBL + 255) / 256, 256>>>(eli);
    zero_fill_k<<<(NNODES + 255) / 256, 256>>>();
    hist_k<<<(ETOT + 255) / 256, 256>>>();
    scan_k<<<1, 1024>>>();
    scatter_k<<<(ETOT + 255) / 256, 256>>>();

    dim3 gemm_grid_conv(DD / 64, (NNODES + 63) / 64);

    // ---- layer 1 ----
    gemm64<false, false><<<gemm_grid_conv, 256>>>(x, W1, hptr, NNODES, FIN, DD,
                                                  nullptr, nullptr, nullptr);
    attn_logits<<<NNODES, 128>>>(as1, ad1);
    attn_softmax_k<<<(NNODES + 7) / 8, 256>>>();
    aggregate_k<<<NNODES, 256>>>(b1);

    // ---- layer 2 ----
    gemm64<false, false><<<gemm_grid_conv, 256>>>(zptr, W2, hptr, NNODES, DD, DD,
                                                  nullptr, nullptr, nullptr);
    attn_logits<<<NNODES, 128>>>(as2, ad2);
    attn_softmax_k<<<(NNODES + 7) / 8, 256>>>();
    aggregate_k<<<NNODES, 256>>>(b2);

    // ---- scorer ----
    dim3 gemm_grid_sc(CC / 64, (NLBL + 63) / 64);
    gemm64<true, true><<<gemm_grid_sc, 256>>>(zptr, Ws1, hidptr, NLBL, 2 * DD, CC,
                                              luptr, lvptr, bs1);
    final_score_k<<<(NLBL + 7) / 8, 256>>>(hidptr, Ws2, bs2, out);
}

// round 4
// speedup vs baseline: 2.0441x; 2.0441x over previous
#include <cuda_runtime.h>
#include <math.h>
#include <stdint.h>

#define NNODES 50000
#define NEDGES 800000
#define ETOT   (NEDGES + NNODES)
#define NLBL   100000
#define FIN    128
#define HH     4
#define CC     64
#define DD     256

// ---------------- scratch (device globals; no allocation allowed) ----------
__device__ int   g_flag64_e;
__device__ int   g_flag64_l;
__device__ int   g_rowptr[NNODES + 1];
__device__ int   g_fill[NNODES];
__device__ int   g_incl[NNODES];
__device__ int   g_bsum[256];
__device__ int   g_csr_src[ETOT];
__device__ int   g_esrc[ETOT];
__device__ int   g_edst[ETOT];
__device__ int   g_lu[NLBL];
__device__ int   g_lv[NLBL];
__device__ float g_hbuf[(size_t)NNODES * DD];   // GEMM output / agg input
__device__ float g_zbuf[(size_t)NNODES * DD];   // agg output / next GEMM input
__device__ float g_als[NNODES * HH];
__device__ float g_ald[NNODES * HH];
__device__ float g_alpha[(size_t)ETOT * HH];    // CSR-ordered attention weights
__device__ float g_pr[(size_t)NNODES * 128];    // scorer P|R per node
__device__ float g_Wt1[256 * 128];              // W1^T  [256][128]
__device__ float g_Wt2[256 * 256];              // W2^T  [256][256]
__device__ float g_Wts[128 * 256];              // [Ws1_top|Ws1_bot]^T [128][256]

// ============================ helpers =======================================
__device__ __forceinline__ uint32_t f2tf32(float x) {
    uint32_t u;
    asm("cvt.rna.tf32.f32 %0, %1;" : "=r"(u) : "f"(x));
    return u;
}

__device__ __forceinline__ void mma1688(float& c0, float& c1, float& c2, float& c3,
                                        uint32_t a0, uint32_t a1, uint32_t a2, uint32_t a3,
                                        uint32_t b0, uint32_t b1) {
    asm volatile(
        "mma.sync.aligned.m16n8k8.row.col.f32.tf32.tf32.f32 "
        "{%0,%1,%2,%3}, {%4,%5,%6,%7}, {%8,%9}, {%0,%1,%2,%3};"
        : "+f"(c0), "+f"(c1), "+f"(c2), "+f"(c3)
        : "r"(a0), "r"(a1), "r"(a2), "r"(a3), "r"(b0), "r"(b1));
}

// ---------------- dtype detection (int64 vs int32 edge arrays) -------------
__device__ __forceinline__ int check_is_i64(const long long* q) {
    int ok = 1;
#pragma unroll
    for (int i = 0; i < 8; i++) {
        long long v = q[i];
        if (v < 0 || v >= NNODES) ok = 0;
    }
    return ok;
}

__global__ void detect_dtype(const void* ei, const void* eli) {
    g_flag64_e = check_is_i64((const long long*)ei);
    g_flag64_l = check_is_i64((const long long*)eli);
}

// ---------------- edge conversion + self loops ------------------------------
__global__ void build_edges(const void* ei) {
    int i = blockIdx.x * blockDim.x + threadIdx.x;
    if (i >= ETOT) return;
    int s, d;
    if (i < NEDGES) {
        if (g_flag64_e) {
            const long long* q = (const long long*)ei;
            s = (int)q[i]; d = (int)q[NEDGES + i];
        } else {
            const int* q = (const int*)ei;
            s = q[i]; d = q[NEDGES + i];
        }
    } else {
        s = i - NEDGES; d = s;   // self loop
    }
    g_esrc[i] = s; g_edst[i] = d;
}

__global__ void build_labels(const void* eli) {
    int i = blockIdx.x * blockDim.x + threadIdx.x;
    if (i >= NLBL) return;
    if (g_flag64_l) {
        const long long* q = (const long long*)eli;
        g_lu[i] = (int)q[i]; g_lv[i] = (int)q[NLBL + i];
    } else {
        const int* q = (const int*)eli;
        g_lu[i] = q[i]; g_lv[i] = q[NLBL + i];
    }
}

// ---------------- CSR build -------------------------------------------------
__global__ void zero_fill_k() {
    int i = blockIdx.x * blockDim.x + threadIdx.x;
    if (i < NNODES) g_fill[i] = 0;
}

__global__ void hist_k() {
    int i = blockIdx.x * blockDim.x + threadIdx.x;
    if (i < ETOT) atomicAdd(&g_fill[g_edst[i]], 1);
}

// hierarchical scan: block inclusive scans
__global__ void scan1_k() {
    __shared__ int sh[256];
    int t = threadIdx.x;
    int i = blockIdx.x * 256 + t;
    int v = (i < NNODES) ? g_fill[i] : 0;
    sh[t] = v; __syncthreads();
    for (int o = 1; o < 256; o <<= 1) {
        int a = (t >= o) ? sh[t - o] : 0;
        __syncthreads();
        sh[t] += a;
        __syncthreads();
    }
    if (i < NNODES) g_incl[i] = sh[t];
    if (t == 255) g_bsum[blockIdx.x] = sh[255];
}

__global__ void scan2_k(int nb) {
    __shared__ int sh[256];
    int t = threadIdx.x;
    int v = (t < nb) ? g_bsum[t] : 0;
    sh[t] = v; __syncthreads();
    for (int o = 1; o < 256; o <<= 1) {
        int a = (t >= o) ? sh[t - o] : 0;
        __syncthreads();
        sh[t] += a;
        __syncthreads();
    }
    if (t < nb) g_bsum[t] = sh[t] - v;   // exclusive
}

__global__ void scan3_k() {
    int i = blockIdx.x * blockDim.x + threadIdx.x;
    if (i >= NNODES) return;
    int tot = g_bsum[i >> 8] + g_incl[i];
    int orig = g_fill[i];
    g_rowptr[i + 1] = tot;
    g_fill[i] = tot - orig;              // exclusive offsets for scatter
    if (i == 0) g_rowptr[0] = 0;
}

__global__ void scatter_k() {
    int i = blockIdx.x * blockDim.x + threadIdx.x;
    if (i >= ETOT) return;
    int pos = atomicAdd(&g_fill[g_edst[i]], 1);
    g_csr_src[pos] = g_esrc[i];
}

// ---------------- weight transposes ----------------------------------------
__global__ void transpose_k(const float* __restrict__ src, float* __restrict__ dst,
                            int K, int Nc) {
    int i = blockIdx.x * blockDim.x + threadIdx.x;
    if (i >= K * Nc) return;
    int n = i / K, k = i - n * K;
    dst[i] = src[k * Nc + n];
}

__global__ void build_wts_k(const float* __restrict__ Ws1) {
    int i = blockIdx.x * blockDim.x + threadIdx.x;
    if (i >= 128 * 256) return;
    int n = i >> 8, k = i & 255;
    g_Wts[i] = (n < 64) ? Ws1[k * 64 + n] : Ws1[(256 + k) * 64 + (n - 64)];
}

// ---------------- tf32 mma.sync GEMM ----------------------------------------
// C[M,NTR] = A[M,KDIM] @ Bt[NTR,KDIM]^T   (Bt row-major, K contiguous)
// Block tile 128x64, 8 warps (4 in M x 2 in N), warp tile 32x32.
template <int KDIM, int NTR>
__global__ void __launch_bounds__(256) gemm_mma(
    const float* __restrict__ A, const float* __restrict__ Bt,
    float* __restrict__ C, int M)
{
    // pitch 36 (floats) -> fragment reads conflict-free: bank = (4g+t) mod 32
    __shared__ uint32_t As[128 * 36];
    __shared__ uint32_t Bs[64 * 36];

    int tid = threadIdx.x;
    int wid = tid >> 5, lane = tid & 31;
    int warp_m = wid & 3, warp_n = wid >> 2;
    int g = lane >> 2, t = lane & 3;

    int rowBase = blockIdx.y * 128;
    int colBase = blockIdx.x * 64;

    float c[2][4][4];
#pragma unroll
    for (int i = 0; i < 2; i++)
#pragma unroll
        for (int j = 0; j < 4; j++)
#pragma unroll
            for (int k = 0; k < 4; k++) c[i][j][k] = 0.f;

    for (int kc = 0; kc < KDIM / 32; kc++) {
        int k0 = kc * 32;
        // stage A: 128 rows x 8 float4
#pragma unroll
        for (int j = 0; j < 4; j++) {
            int idx = tid + 256 * j;          // 0..1023
            int r = idx >> 3, q = idx & 7;
            int gr = rowBase + r;
            float4 v = (gr < M) ? *(const float4*)(A + (size_t)gr * KDIM + k0 + q * 4)
                                : make_float4(0.f, 0.f, 0.f, 0.f);
            uint4 u = { f2tf32(v.x), f2tf32(v.y), f2tf32(v.z), f2tf32(v.w) };
            *(uint4*)&As[r * 36 + q * 4] = u;
        }
        // stage B: 64 rows x 8 float4
#pragma unroll
        for (int j = 0; j < 2; j++) {
            int idx = tid + 256 * j;          // 0..511
            int r = idx >> 3, q = idx & 7;
            float4 v = *(const float4*)(Bt + (size_t)(colBase + r) * KDIM + k0 + q * 4);
            uint4 u = { f2tf32(v.x), f2tf32(v.y), f2tf32(v.z), f2tf32(v.w) };
            *(uint4*)&Bs[r * 36 + q * 4] = u;
        }
        __syncthreads();

#pragma unroll
        for (int ks = 0; ks < 4; ks++) {
            int kk = ks * 8;
            uint32_t a[2][4];
#pragma unroll
            for (int tm = 0; tm < 2; tm++) {
                int r0 = warp_m * 32 + tm * 16;
                a[tm][0] = As[(r0 + g) * 36 + kk + t];
                a[tm][1] = As[(r0 + g + 8) * 36 + kk + t];
                a[tm][2] = As[(r0 + g) * 36 + kk + t + 4];
                a[tm][3] = As[(r0 + g + 8) * 36 + kk + t + 4];
            }
            uint32_t b[4][2];
#pragma unroll
            for (int tn = 0; tn < 4; tn++) {
                int n0 = warp_n * 32 + tn * 8 + g;
                b[tn][0] = Bs[n0 * 36 + kk + t];
                b[tn][1] = Bs[n0 * 36 + kk + t + 4];
            }
#pragma unroll
            for (int tm = 0; tm < 2; tm++)
#pragma unroll
                for (int tn = 0; tn < 4; tn++)
                    mma1688(c[tm][tn][0], c[tm][tn][1], c[tm][tn][2], c[tm][tn][3],
                            a[tm][0], a[tm][1], a[tm][2], a[tm][3],
                            b[tn][0], b[tn][1]);
        }
        __syncthreads();
    }

    // epilogue
#pragma unroll
    for (int tm = 0; tm < 2; tm++) {
        int r0 = rowBase + warp_m * 32 + tm * 16 + g;
        int r1 = r0 + 8;
#pragma unroll
        for (int tn = 0; tn < 4; tn++) {
            int col = colBase + warp_n * 32 + tn * 8 + t * 2;
            if (r0 < M)
                *(float2*)(C + (size_t)r0 * NTR + col) = make_float2(c[tm][tn][0], c[tm][tn][1]);
            if (r1 < M)
                *(float2*)(C + (size_t)r1 * NTR + col) = make_float2(c[tm][tn][2], c[tm][tn][3]);
        }
    }
}

// ---------------- attention logits: al[n][h] = <h[n,h,:], a[h,:]> -----------
__global__ void attn_logits(const float* __restrict__ a_src,
                            const float* __restrict__ a_dst) {
    int n = blockIdx.x;
    int w = threadIdx.x >> 5, lane = threadIdx.x & 31;
    const float* hr = g_hbuf + (size_t)n * 256 + w * 64;
    float x0 = hr[lane], x1 = hr[lane + 32];
    float s = x0 * a_src[w * 64 + lane] + x1 * a_src[w * 64 + lane + 32];
    float d = x0 * a_dst[w * 64 + lane] + x1 * a_dst[w * 64 + lane + 32];
#pragma unroll
    for (int o = 16; o; o >>= 1) {
        s += __shfl_xor_sync(0xffffffffu, s, o);
        d += __shfl_xor_sync(0xffffffffu, d, o);
    }
    if (!lane) { g_als[n * 4 + w] = s; g_ald[n * 4 + w] = d; }
}

// ---------------- per-node softmax over incoming edges (warp/node) ----------
__global__ void attn_softmax_k() {
    int node = (blockIdx.x * blockDim.x + threadIdx.x) >> 5;
    int lane = threadIdx.x & 31;
    if (node >= NNODES) return;
    int beg = g_rowptr[node], end = g_rowptr[node + 1];

    float4 adv = *(const float4*)&g_ald[node * 4];
    float ad[4] = {adv.x, adv.y, adv.z, adv.w};

    float mx[4] = {-INFINITY, -INFINITY, -INFINITY, -INFINITY};
    for (int k = beg + lane; k < end; k += 32) {
        int s = g_csr_src[k];
        float4 av = *(const float4*)&g_als[s * 4];
        float e[4] = {av.x + ad[0], av.y + ad[1], av.z + ad[2], av.w + ad[3]};
#pragma unroll
        for (int h = 0; h < 4; h++) {
            float v = e[h] > 0.f ? e[h] : 0.2f * e[h];
            mx[h] = fmaxf(mx[h], v);
        }
    }
#pragma unroll
    for (int h = 0; h < 4; h++)
#pragma unroll
        for (int o = 16; o; o >>= 1)
            mx[h] = fmaxf(mx[h], __shfl_xor_sync(0xffffffffu, mx[h], o));

    float sm[4] = {0.f, 0.f, 0.f, 0.f};
    for (int k = beg + lane; k < end; k += 32) {
        int s = g_csr_src[k];
        float4 av = *(const float4*)&g_als[s * 4];
        float e[4] = {av.x + ad[0], av.y + ad[1], av.z + ad[2], av.w + ad[3]};
        float p[4];
#pragma unroll
        for (int h = 0; h < 4; h++) {
            float v = e[h] > 0.f ? e[h] : 0.2f * e[h];
            p[h] = __expf(v - mx[h]);
            sm[h] += p[h];
        }
        *(float4*)&g_alpha[(size_t)k * 4] = make_float4(p[0], p[1], p[2], p[3]);
    }
#pragma unroll
    for (int h = 0; h < 4; h++) {
#pragma unroll
        for (int o = 16; o; o >>= 1)
            sm[h] += __shfl_xor_sync(0xffffffffu, sm[h], o);
        sm[h] = 1.f / sm[h];
    }
    for (int k = beg + lane; k < end; k += 32) {
        float4 p = *(const float4*)&g_alpha[(size_t)k * 4];
        p.x *= sm[0]; p.y *= sm[1]; p.z *= sm[2]; p.w *= sm[3];
        *(float4*)&g_alpha[(size_t)k * 4] = p;
    }
}

// ---------------- pull aggregation + bias + ELU (4 nodes/block, float4) -----
__global__ void aggregate_k(const float* __restrict__ bias) {
    int g = threadIdx.x >> 6, t = threadIdx.x & 63;
    int n = blockIdx.x * 4 + g;
    if (n >= NNODES) return;
    int hh = t >> 4;
    int beg = g_rowptr[n], end = g_rowptr[n + 1];
    float4 acc = make_float4(0.f, 0.f, 0.f, 0.f);
#pragma unroll 2
    for (int k = beg; k < end; k++) {
        int s = g_csr_src[k];
        float w = g_alpha[(size_t)k * 4 + hh];
        float4 hv = *(const float4*)&g_hbuf[(size_t)s * 256 + t * 4];
        acc.x = fmaf(w, hv.x, acc.x);
        acc.y = fmaf(w, hv.y, acc.y);
        acc.z = fmaf(w, hv.z, acc.z);
        acc.w = fmaf(w, hv.w, acc.w);
    }
    float4 bv = *(const float4*)&bias[t * 4];
    float4 o;
    o.x = acc.x + bv.x; o.x = o.x > 0.f ? o.x : (__expf(o.x) - 1.f);
    o.y = acc.y + bv.y; o.y = o.y > 0.f ? o.y : (__expf(o.y) - 1.f);
    o.z = acc.z + bv.z; o.z = o.z > 0.f ? o.z : (__expf(o.z) - 1.f);
    o.w = acc.w + bv.w; o.w = o.w > 0.f ? o.w : (__expf(o.w) - 1.f);
    *(float4*)&g_zbuf[(size_t)n * 256 + t * 4] = o;
}

// ---------------- fused scorer: out = relu(P[u]+R[v]+bs1) . Ws2 + bs2 -------
__global__ void score_k(const float* __restrict__ bs1, const float* __restrict__ Ws2,
                        const float* __restrict__ bs2, float* __restrict__ out) {
    int e = (blockIdx.x * blockDim.x + threadIdx.x) >> 5;
    int lane = threadIdx.x & 31;
    if (e >= NLBL) return;
    int u = g_lu[e], v = g_lv[e];
    const float* pu = g_pr + (size_t)u * 128;
    const float* rv = g_pr + (size_t)v * 128 + 64;
    float s = 0.f;
#pragma unroll
    for (int j = 0; j < 2; j++) {
        int c = lane + j * 32;
        float h = pu[c] + rv[c] + bs1[c];
        h = fmaxf(h, 0.f);
        s = fmaf(h, Ws2[c], s);
    }
#pragma unroll
    for (int o = 16; o; o >>= 1) s += __shfl_xor_sync(0xffffffffu, s, o);
    if (!lane) out[e] = s + bs2[0];
}

// ---------------- launcher --------------------------------------------------
extern "C" void kernel_launch(void* const* d_in, const int* in_sizes, int n_in,
                              void* d_out, int out_size) {
    const float* x   = (const float*)d_in[0];
    const void*  ei  = d_in[1];
    const void*  eli = d_in[2];
    const float* W1  = (const float*)d_in[3];
    const float* as1 = (const float*)d_in[4];
    const float* ad1 = (const float*)d_in[5];
    const float* b1  = (const float*)d_in[6];
    const float* W2  = (const float*)d_in[7];
    const float* as2 = (const float*)d_in[8];
    const float* ad2 = (const float*)d_in[9];
    const float* b2  = (const float*)d_in[10];
    const float* Ws1 = (const float*)d_in[11];
    const float* bs1 = (const float*)d_in[12];
    const float* Ws2 = (const float*)d_in[13];
    const float* bs2 = (const float*)d_in[14];
    float* out = (float*)d_out;

    float *hptr, *zptr, *prptr, *wt1, *wt2, *wts;
    cudaGetSymbolAddress((void**)&hptr, g_hbuf);
    cudaGetSymbolAddress((void**)&zptr, g_zbuf);
    cudaGetSymbolAddress((void**)&prptr, g_pr);
    cudaGetSymbolAddress((void**)&wt1, g_Wt1);
    cudaGetSymbolAddress((void**)&wt2, g_Wt2);
    cudaGetSymbolAddress((void**)&wts, g_Wts);

    // graph prep
    detect_dtype<<<1, 1>>>(ei, eli);
    build_edges<<<(ETOT + 255) / 256, 256>>>(ei);
    build_labels<<<(NLBL + 255) / 256, 256>>>(eli);
    zero_fill_k<<<(NNODES + 255) / 256, 256>>>();
    hist_k<<<(ETOT + 255) / 256, 256>>>();
    int nb = (NNODES + 255) / 256;   // 196
    scan1_k<<<nb, 256>>>();
    scan2_k<<<1, 256>>>(nb);
    scan3_k<<<(NNODES + 255) / 256, 256>>>();
    scatter_k<<<(ETOT + 255) / 256, 256>>>();

    // weight transposes
    transpose_k<<<(256 * 128 + 255) / 256, 256>>>(W1, wt1, 128, 256);
    transpose_k<<<(256 * 256 + 255) / 256, 256>>>(W2, wt2, 256, 256);
    build_wts_k<<<(128 * 256 + 255) / 256, 256>>>(Ws1);

    int mrows = (NNODES + 127) / 128;   // 391

    // ---- layer 1 ----
    gemm_mma<128, 256><<<dim3(4, mrows), 256>>>(x, wt1, hptr, NNODES);
    attn_logits<<<NNODES, 128>>>(as1, ad1);
    attn_softmax_k<<<(NNODES + 7) / 8, 256>>>();
    aggregate_k<<<(NNODES + 3) / 4, 256>>>(b1);

    // ---- layer 2 ----
    gemm_mma<256, 256><<<dim3(4, mrows), 256>>>(zptr, wt2, hptr, NNODES);
    attn_logits<<<NNODES, 128>>>(as2, ad2);
    attn_softmax_k<<<(NNODES + 7) / 8, 256>>>();
    aggregate_k<<<(NNODES + 3) / 4, 256>>>(b2);

    // ---- scorer ----
    gemm_mma<256, 128><<<dim3(2, mrows), 256>>>(zptr, wts, prptr, NNODES);
    score_k<<<(NLBL + 7) / 8, 256>>>(bs1, Ws2, bs2, out);
}

// round 5
// speedup vs baseline: 2.6965x; 1.3191x over previous
#include <cuda_runtime.h>
#include <math.h>
#include <stdint.h>

#define NNODES 50000
#define NEDGES 800000
#define ETOT   (NEDGES + NNODES)
#define NLBL   100000
#define FIN    128
#define HH     4
#define CC     64
#define DD     256

// ---------------- scratch (device globals; no allocation allowed) ----------
__device__ int   g_flag64_e;
__device__ int   g_flag64_l;
__device__ int   g_rowptr[NNODES + 1];
__device__ int   g_fill[NNODES];
__device__ int   g_incl[NNODES];
__device__ int   g_bsum[256];
__device__ int   g_csr_src[ETOT];
__device__ int   g_esrc[ETOT];
__device__ int   g_edst[ETOT];
__device__ int   g_lu[NLBL];
__device__ int   g_lv[NLBL];
__device__ float g_hbuf[(size_t)NNODES * DD];   // GEMM output / agg input
__device__ float g_zbuf[(size_t)NNODES * DD];   // agg output / next GEMM input
__device__ float g_als[NNODES * HH];
__device__ float g_ald[NNODES * HH];
__device__ float g_inv[NNODES * HH];            // 1/softmax denom per node,head
__device__ float g_alpha[(size_t)ETOT * HH];    // CSR-ordered UNNORMALIZED p
__device__ float g_pr[(size_t)NNODES * 128];    // scorer P|R per node
__device__ float g_Wt1[256 * 128];              // W1^T  [256][128]
__device__ float g_Wt2[256 * 256];              // W2^T  [256][256]
__device__ float g_Wts[128 * 256];              // [Ws1_top|Ws1_bot]^T [128][256]

// ============================ helpers =======================================
__device__ __forceinline__ uint32_t f2tf32(float x) {
    uint32_t u;
    asm("cvt.rna.tf32.f32 %0, %1;" : "=r"(u) : "f"(x));
    return u;
}

__device__ __forceinline__ void mma1688(float& c0, float& c1, float& c2, float& c3,
                                        uint32_t a0, uint32_t a1, uint32_t a2, uint32_t a3,
                                        uint32_t b0, uint32_t b1) {
    asm volatile(
        "mma.sync.aligned.m16n8k8.row.col.f32.tf32.tf32.f32 "
        "{%0,%1,%2,%3}, {%4,%5,%6,%7}, {%8,%9}, {%0,%1,%2,%3};"
        : "+f"(c0), "+f"(c1), "+f"(c2), "+f"(c3)
        : "r"(a0), "r"(a1), "r"(a2), "r"(a3), "r"(b0), "r"(b1));
}

// ---------------- init: zero hist + dtype detection --------------------------
__device__ __forceinline__ int check_is_i64(const long long* q) {
    int ok = 1;
#pragma unroll
    for (int i = 0; i < 8; i++) {
        long long v = q[i];
        if (v < 0 || v >= NNODES) ok = 0;
    }
    return ok;
}

__global__ void init_k(const void* ei, const void* eli) {
    int i = blockIdx.x * blockDim.x + threadIdx.x;
    if (i < NNODES) g_fill[i] = 0;
    if (i == 0) {
        g_flag64_e = check_is_i64((const long long*)ei);
        g_flag64_l = check_is_i64((const long long*)eli);
    }
}

// ---------------- edge conversion + self loops + histogram ------------------
__global__ void build_edges(const void* ei) {
    int i = blockIdx.x * blockDim.x + threadIdx.x;
    if (i >= ETOT) return;
    int s, d;
    if (i < NEDGES) {
        if (g_flag64_e) {
            const long long* q = (const long long*)ei;
            s = (int)q[i]; d = (int)q[NEDGES + i];
        } else {
            const int* q = (const int*)ei;
            s = q[i]; d = q[NEDGES + i];
        }
    } else {
        s = i - NEDGES; d = s;   // self loop
    }
    g_esrc[i] = s; g_edst[i] = d;
    atomicAdd(&g_fill[d], 1);
}

__global__ void build_labels(const void* eli) {
    int i = blockIdx.x * blockDim.x + threadIdx.x;
    if (i >= NLBL) return;
    if (g_flag64_l) {
        const long long* q = (const long long*)eli;
        g_lu[i] = (int)q[i]; g_lv[i] = (int)q[NLBL + i];
    } else {
        const int* q = (const int*)eli;
        g_lu[i] = q[i]; g_lv[i] = q[NLBL + i];
    }
}

// ---------------- CSR build: hierarchical scan -------------------------------
__global__ void scan1_k() {
    __shared__ int sh[256];
    int t = threadIdx.x;
    int i = blockIdx.x * 256 + t;
    int v = (i < NNODES) ? g_fill[i] : 0;
    sh[t] = v; __syncthreads();
    for (int o = 1; o < 256; o <<= 1) {
        int a = (t >= o) ? sh[t - o] : 0;
        __syncthreads();
        sh[t] += a;
        __syncthreads();
    }
    if (i < NNODES) g_incl[i] = sh[t];
    if (t == 255) g_bsum[blockIdx.x] = sh[255];
}

__global__ void scan2_k(int nb) {
    __shared__ int sh[256];
    int t = threadIdx.x;
    int v = (t < nb) ? g_bsum[t] : 0;
    sh[t] = v; __syncthreads();
    for (int o = 1; o < 256; o <<= 1) {
        int a = (t >= o) ? sh[t - o] : 0;
        __syncthreads();
        sh[t] += a;
        __syncthreads();
    }
    if (t < nb) g_bsum[t] = sh[t] - v;   // exclusive
}

__global__ void scan3_k() {
    int i = blockIdx.x * blockDim.x + threadIdx.x;
    if (i >= NNODES) return;
    int tot = g_bsum[i >> 8] + g_incl[i];
    int orig = g_fill[i];
    g_rowptr[i + 1] = tot;
    g_fill[i] = tot - orig;              // exclusive offsets for scatter
    if (i == 0) g_rowptr[0] = 0;
}

__global__ void scatter_k() {
    int i = blockIdx.x * blockDim.x + threadIdx.x;
    if (i >= ETOT) return;
    int pos = atomicAdd(&g_fill[g_edst[i]], 1);
    g_csr_src[pos] = g_esrc[i];
}

// ---------------- weight prep (all transposes in one kernel) ----------------
__global__ void prep_weights_k(const float* __restrict__ W1,
                               const float* __restrict__ W2,
                               const float* __restrict__ Ws1) {
    int i = blockIdx.x * blockDim.x + threadIdx.x;
    // Wt1: [256][128] from W1[128][256]
    if (i < 256 * 128) {
        int n = i >> 7, k = i & 127;
        g_Wt1[i] = W1[k * 256 + n];
    }
    // Wt2: [256][256] from W2[256][256]
    int j = i - 256 * 128;
    if (j >= 0 && j < 256 * 256) {
        int n = j >> 8, k = j & 255;
        g_Wt2[j] = W2[k * 256 + n];
    }
    // Wts: [128][256]: rows 0..63 = Ws1_top^T, 64..127 = Ws1_bot^T
    int l = i - 256 * 128 - 256 * 256;
    if (l >= 0 && l < 128 * 256) {
        int n = l >> 8, k = l & 255;
        g_Wts[l] = (n < 64) ? Ws1[k * 64 + n] : Ws1[(256 + k) * 64 + (n - 64)];
    }
}

// ---------------- tf32 mma.sync GEMM with register prefetch -----------------
// C[M,NTR] = A[M,KDIM] @ Bt[NTR,KDIM]^T   (Bt row-major, K contiguous)
// Block tile 128x64, 8 warps (4 in M x 2 in N), warp tile 32x32.
// LOGITS (NTR==256 layer GEMMs): each col-block spans exactly one head
// (64 cols); fused reduction writes als/ald for that head — no atomics.
template <int KDIM, int NTR, bool LOGITS>
__global__ void __launch_bounds__(256) gemm_mma(
    const float* __restrict__ A, const float* __restrict__ Bt,
    float* __restrict__ C, int M,
    const float* __restrict__ a_src, const float* __restrict__ a_dst,
    float* __restrict__ als, float* __restrict__ ald)
{
    // pitch 36 (floats) -> fragment reads conflict-free: bank = (4g+t) mod 32
    __shared__ uint32_t As[128 * 36];
    __shared__ uint32_t Bs[64 * 36];
    __shared__ float red[4][128];    // [warp_n*2 + (src/dst)][row]

    int tid = threadIdx.x;
    int wid = tid >> 5, lane = tid & 31;
    int warp_m = wid & 3, warp_n = wid >> 2;
    int g = lane >> 2, t = lane & 3;

    int rowBase = blockIdx.y * 128;
    int colBase = blockIdx.x * 64;

    float c[2][4][4];
#pragma unroll
    for (int i = 0; i < 2; i++)
#pragma unroll
        for (int j = 0; j < 4; j++)
#pragma unroll
            for (int k = 0; k < 4; k++) c[i][j][k] = 0.f;

    constexpr int NC = KDIM / 32;
    // prefetch registers
    float4 ra[4], rb[2];
    int ar = tid >> 3, aq = tid & 7;           // A: row 0..127 (two passes), q
    {
        int k0 = 0;
#pragma unroll
        for (int j = 0; j < 4; j++) {
            int idx = tid + 256 * j;
            int r = idx >> 3, q = idx & 7;
            int gr = rowBase + r;
            ra[j] = (gr < M) ? *(const float4*)(A + (size_t)gr * KDIM + k0 + q * 4)
                             : make_float4(0.f, 0.f, 0.f, 0.f);
        }
#pragma unroll
        for (int j = 0; j < 2; j++) {
            int idx = tid + 256 * j;
            int r = idx >> 3, q = idx & 7;
            rb[j] = *(const float4*)(Bt + (size_t)(colBase + r) * KDIM + k0 + q * 4);
        }
    }

    for (int kc = 0; kc < NC; kc++) {
        // store prefetched regs (with tf32 convert) to smem
#pragma unroll
        for (int j = 0; j < 4; j++) {
            int idx = tid + 256 * j;
            int r = idx >> 3, q = idx & 7;
            uint4 u = { f2tf32(ra[j].x), f2tf32(ra[j].y), f2tf32(ra[j].z), f2tf32(ra[j].w) };
            *(uint4*)&As[r * 36 + q * 4] = u;
        }
#pragma unroll
        for (int j = 0; j < 2; j++) {
            int idx = tid + 256 * j;
            int r = idx >> 3, q = idx & 7;
            uint4 u = { f2tf32(rb[j].x), f2tf32(rb[j].y), f2tf32(rb[j].z), f2tf32(rb[j].w) };
            *(uint4*)&Bs[r * 36 + q * 4] = u;
        }
        __syncthreads();

        // issue next chunk's global loads (overlap with compute below)
        if (kc + 1 < NC) {
            int k0 = (kc + 1) * 32;
#pragma unroll
            for (int j = 0; j < 4; j++) {
                int idx = tid + 256 * j;
                int r = idx >> 3, q = idx & 7;
                int gr = rowBase + r;
                ra[j] = (gr < M) ? *(const float4*)(A + (size_t)gr * KDIM + k0 + q * 4)
                                 : make_float4(0.f, 0.f, 0.f, 0.f);
            }
#pragma unroll
            for (int j = 0; j < 2; j++) {
                int idx = tid + 256 * j;
                int r = idx >> 3, q = idx & 7;
                rb[j] = *(const float4*)(Bt + (size_t)(colBase + r) * KDIM + k0 + q * 4);
            }
        }

#pragma unroll
        for (int ks = 0; ks < 4; ks++) {
            int kk = ks * 8;
            uint32_t a[2][4];
#pragma unroll
            for (int tm = 0; tm < 2; tm++) {
                int r0 = warp_m * 32 + tm * 16;
                a[tm][0] = As[(r0 + g) * 36 + kk + t];
                a[tm][1] = As[(r0 + g + 8) * 36 + kk + t];
                a[tm][2] = As[(r0 + g) * 36 + kk + t + 4];
                a[tm][3] = As[(r0 + g + 8) * 36 + kk + t + 4];
            }
            uint32_t b[4][2];
#pragma unroll
            for (int tn = 0; tn < 4; tn++) {
                int n0 = warp_n * 32 + tn * 8 + g;
                b[tn][0] = Bs[n0 * 36 + kk + t];
                b[tn][1] = Bs[n0 * 36 + kk + t + 4];
            }
#pragma unroll
            for (int tm = 0; tm < 2; tm++)
#pragma unroll
                for (int tn = 0; tn < 4; tn++)
                    mma1688(c[tm][tn][0], c[tm][tn][1], c[tm][tn][2], c[tm][tn][3],
                            a[tm][0], a[tm][1], a[tm][2], a[tm][3],
                            b[tn][0], b[tn][1]);
        }
        __syncthreads();
    }

    // epilogue: store C (+ fused logits)
    float ps[2][2], pd[2][2];     // [tm][r0/r1]
    if (LOGITS) {
#pragma unroll
        for (int tm = 0; tm < 2; tm++)
            ps[tm][0] = ps[tm][1] = pd[tm][0] = pd[tm][1] = 0.f;
    }
#pragma unroll
    for (int tm = 0; tm < 2; tm++) {
        int r0 = rowBase + warp_m * 32 + tm * 16 + g;
        int r1 = r0 + 8;
#pragma unroll
        for (int tn = 0; tn < 4; tn++) {
            int col = colBase + warp_n * 32 + tn * 8 + t * 2;
            if (LOGITS) {
                float s0 = a_src[col], s1 = a_src[col + 1];
                float d0 = a_dst[col], d1 = a_dst[col + 1];
                ps[tm][0] += c[tm][tn][0] * s0 + c[tm][tn][1] * s1;
                pd[tm][0] += c[tm][tn][0] * d0 + c[tm][tn][1] * d1;
                ps[tm][1] += c[tm][tn][2] * s0 + c[tm][tn][3] * s1;
                pd[tm][1] += c[tm][tn][2] * d0 + c[tm][tn][3] * d1;
            }
            if (r0 < M)
                *(float2*)(C + (size_t)r0 * NTR + col) = make_float2(c[tm][tn][0], c[tm][tn][1]);
            if (r1 < M)
                *(float2*)(C + (size_t)r1 * NTR + col) = make_float2(c[tm][tn][2], c[tm][tn][3]);
        }
    }
    if (LOGITS) {
        // reduce over t (4 lanes with same g)
#pragma unroll
        for (int tm = 0; tm < 2; tm++)
#pragma unroll
            for (int rr = 0; rr < 2; rr++) {
#pragma unroll
                for (int o = 1; o < 4; o <<= 1) {
                    ps[tm][rr] += __shfl_xor_sync(0xffffffffu, ps[tm][rr], o);
                    pd[tm][rr] += __shfl_xor_sync(0xffffffffu, pd[tm][rr], o);
                }
            }
        __syncthreads();   // reuse red[] safely after compute
        if (t == 0) {
#pragma unroll
            for (int tm = 0; tm < 2; tm++) {
                int rl = warp_m * 32 + tm * 16 + g;
                red[warp_n * 2 + 0][rl]     = ps[tm][0];
                red[warp_n * 2 + 0][rl + 8] = ps[tm][1];
                red[warp_n * 2 + 1][rl]     = pd[tm][0];
                red[warp_n * 2 + 1][rl + 8] = pd[tm][1];
            }
        }
        __syncthreads();
        if (tid < 128) {
            int row = rowBase + tid;
            if (row < M) {
                int h = blockIdx.x;   // 64-col block == one head
                als[row * 4 + h] = red[0][tid] + red[2][tid];
                ald[row * 4 + h] = red[1][tid] + red[3][tid];
            }
        }
    }
}

// ---------------- per-node softmax (2 passes, unnormalized p + inv denom) ---
__global__ void attn_softmax_k() {
    int node = (blockIdx.x * blockDim.x + threadIdx.x) >> 5;
    int lane = threadIdx.x & 31;
    if (node >= NNODES) return;
    int beg = g_rowptr[node], end = g_rowptr[node + 1];

    float4 adv = *(const float4*)&g_ald[node * 4];
    float ad[4] = {adv.x, adv.y, adv.z, adv.w};

    float mx[4] = {-INFINITY, -INFINITY, -INFINITY, -INFINITY};
    for (int k = beg + lane; k < end; k += 32) {
        int s = g_csr_src[k];
        float4 av = *(const float4*)&g_als[s * 4];
        float e[4] = {av.x + ad[0], av.y + ad[1], av.z + ad[2], av.w + ad[3]};
#pragma unroll
        for (int h = 0; h < 4; h++) {
            float v = e[h] > 0.f ? e[h] : 0.2f * e[h];
            mx[h] = fmaxf(mx[h], v);
        }
    }
#pragma unroll
    for (int h = 0; h < 4; h++)
#pragma unroll
        for (int o = 16; o; o >>= 1)
            mx[h] = fmaxf(mx[h], __shfl_xor_sync(0xffffffffu, mx[h], o));

    float sm[4] = {0.f, 0.f, 0.f, 0.f};
    for (int k = beg + lane; k < end; k += 32) {
        int s = g_csr_src[k];
        float4 av = *(const float4*)&g_als[s * 4];
        float e[4] = {av.x + ad[0], av.y + ad[1], av.z + ad[2], av.w + ad[3]};
        float p[4];
#pragma unroll
        for (int h = 0; h < 4; h++) {
            float v = e[h] > 0.f ? e[h] : 0.2f * e[h];
            p[h] = __expf(v - mx[h]);
            sm[h] += p[h];
        }
        *(float4*)&g_alpha[(size_t)k * 4] = make_float4(p[0], p[1], p[2], p[3]);
    }
#pragma unroll
    for (int h = 0; h < 4; h++)
#pragma unroll
        for (int o = 16; o; o >>= 1)
            sm[h] += __shfl_xor_sync(0xffffffffu, sm[h], o);
    if (!lane)
        *(float4*)&g_inv[node * 4] = make_float4(1.f / sm[0], 1.f / sm[1],
                                                 1.f / sm[2], 1.f / sm[3]);
}

// ---------------- pull aggregation (scale by inv denom) + bias + ELU --------
__global__ void aggregate_k(const float* __restrict__ bias) {
    int g = threadIdx.x >> 6, t = threadIdx.x & 63;
    int n = blockIdx.x * 4 + g;
    if (n >= NNODES) return;
    int hh = t >> 4;
    int beg = g_rowptr[n], end = g_rowptr[n + 1];
    float4 acc = make_float4(0.f, 0.f, 0.f, 0.f);
#pragma unroll 2
    for (int k = beg; k < end; k++) {
        int s = g_csr_src[k];
        float w = g_alpha[(size_t)k * 4 + hh];
        float4 hv = *(const float4*)&g_hbuf[(size_t)s * 256 + t * 4];
        acc.x = fmaf(w, hv.x, acc.x);
        acc.y = fmaf(w, hv.y, acc.y);
        acc.z = fmaf(w, hv.z, acc.z);
        acc.w = fmaf(w, hv.w, acc.w);
    }
    float inv = g_inv[n * 4 + hh];
    float4 bv = *(const float4*)&bias[t * 4];
    float4 o;
    o.x = fmaf(acc.x, inv, bv.x); o.x = o.x > 0.f ? o.x : (__expf(o.x) - 1.f);
    o.y = fmaf(acc.y, inv, bv.y); o.y = o.y > 0.f ? o.y : (__expf(o.y) - 1.f);
    o.z = fmaf(acc.z, inv, bv.z); o.z = o.z > 0.f ? o.z : (__expf(o.z) - 1.f);
    o.w = fmaf(acc.w, inv, bv.w); o.w = o.w > 0.f ? o.w : (__expf(o.w) - 1.f);
    *(float4*)&g_zbuf[(size_t)n * 256 + t * 4] = o;
}

// ---------------- fused scorer: out = relu(P[u]+R[v]+bs1) . Ws2 + bs2 -------
__global__ void score_k(const float* __restrict__ bs1, const float* __restrict__ Ws2,
                        const float* __restrict__ bs2, float* __restrict__ out) {
    int e = (blockIdx.x * blockDim.x + threadIdx.x) >> 5;
    int lane = threadIdx.x & 31;
    if (e >= NLBL) return;
    int u = g_lu[e], v = g_lv[e];
    const float* pu = g_pr + (size_t)u * 128;
    const float* rv = g_pr + (size_t)v * 128 + 64;
    float s = 0.f;
#pragma unroll
    for (int j = 0; j < 2; j++) {
        int c = lane + j * 32;
        float h = pu[c] + rv[c] + bs1[c];
        h = fmaxf(h, 0.f);
        s = fmaf(h, Ws2[c], s);
    }
#pragma unroll
    for (int o = 16; o; o >>= 1) s += __shfl_xor_sync(0xffffffffu, s, o);
    if (!lane) out[e] = s + bs2[0];
}

// ---------------- launcher --------------------------------------------------
extern "C" void kernel_launch(void* const* d_in, const int* in_sizes, int n_in,
                              void* d_out, int out_size) {
    const float* x   = (const float*)d_in[0];
    const void*  ei  = d_in[1];
    const void*  eli = d_in[2];
    const float* W1  = (const float*)d_in[3];
    const float* as1 = (const float*)d_in[4];
    const float* ad1 = (const float*)d_in[5];
    const float* b1  = (const float*)d_in[6];
    const float* W2  = (const float*)d_in[7];
    const float* as2 = (const float*)d_in[8];
    const float* ad2 = (const float*)d_in[9];
    const float* b2  = (const float*)d_in[10];
    const float* Ws1 = (const float*)d_in[11];
    const float* bs1 = (const float*)d_in[12];
    const float* Ws2 = (const float*)d_in[13];
    const float* bs2 = (const float*)d_in[14];
    float* out = (float*)d_out;

    float *hptr, *zptr, *prptr, *wt1, *wt2, *wts, *alsp, *aldp;
    cudaGetSymbolAddress((void**)&hptr, g_hbuf);
    cudaGetSymbolAddress((void**)&zptr, g_zbuf);
    cudaGetSymbolAddress((void**)&prptr, g_pr);
    cudaGetSymbolAddress((void**)&wt1, g_Wt1);
    cudaGetSymbolAddress((void**)&wt2, g_Wt2);
    cudaGetSymbolAddress((void**)&wts, g_Wts);
    cudaGetSymbolAddress((void**)&alsp, g_als);
    cudaGetSymbolAddress((void**)&aldp, g_ald);

    // graph prep
    init_k<<<(NNODES + 255) / 256, 256>>>(ei, eli);
    build_edges<<<(ETOT + 255) / 256, 256>>>(ei);
    build_labels<<<(NLBL + 255) / 256, 256>>>(eli);
    int nb = (NNODES + 255) / 256;   // 196
    scan1_k<<<nb, 256>>>();
    scan2_k<<<1, 256>>>(nb);
    scan3_k<<<(NNODES + 255) / 256, 256>>>();
    scatter_k<<<(ETOT + 255) / 256, 256>>>();

    // weight prep (one kernel)
    int wtot = 256 * 128 + 256 * 256 + 128 * 256;
    prep_weights_k<<<(wtot + 255) / 256, 256>>>(W1, W2, Ws1);

    int mrows = (NNODES + 127) / 128;   // 391

    // ---- layer 1 ----
    gemm_mma<128, 256, true><<<dim3(4, mrows), 256>>>(x, wt1, hptr, NNODES,
                                                      as1, ad1, alsp, aldp);
    attn_softmax_k<<<(NNODES + 7) / 8, 256>>>();
    aggregate_k<<<(NNODES + 3) / 4, 256>>>(b1);

    // ---- layer 2 ----
    gemm_mma<256, 256, true><<<dim3(4, mrows), 256>>>(zptr, wt2, hptr, NNODES,
                                                      as2, ad2, alsp, aldp);
    attn_softmax_k<<<(NNODES + 7) / 8, 256>>>();
    aggregate_k<<<(NNODES + 3) / 4, 256>>>(b2);

    // ---- scorer ----
    gemm_mma<256, 128, false><<<dim3(2, mrows), 256>>>(zptr, wts, prptr, NNODES,
                                                       nullptr, nullptr, nullptr, nullptr);
    score_k<<<(NLBL + 7) / 8, 256>>>(bs1, Ws2, bs2, out);
}

// round 6
// speedup vs baseline: 3.0706x; 1.1388x over previous
#include <cuda_runtime.h>
#include <cuda_fp16.h>
#include <math.h>
#include <stdint.h>

#define NNODES 50000
#define NEDGES 800000
#define ETOT   (NEDGES + NNODES)
#define NLBL   100000
#define FIN    128
#define HH     4
#define CC     64
#define DD     256

// ---------------- scratch (device globals; no allocation allowed) ----------
__device__ int    g_flag64_e;
__device__ int    g_flag64_l;
__device__ int    g_rowptr[NNODES + 1];
__device__ int    g_fill[NNODES];
__device__ int    g_incl[NNODES];
__device__ int    g_bsum[256];
__device__ int    g_csr_src[ETOT];
__device__ int    g_esrc[ETOT];
__device__ int    g_edst[ETOT];
__device__ int    g_lu[NLBL];
__device__ int    g_lv[NLBL];
__device__ __half g_hbuf[(size_t)NNODES * DD];  // GEMM output (fp16) / agg input
__device__ float  g_zbuf[(size_t)NNODES * DD];  // agg output / next GEMM input
__device__ float  g_als[NNODES * HH];
__device__ float  g_ald[NNODES * HH];
__device__ float  g_inv[NNODES * HH];           // 1/softmax denom per node,head
__device__ float  g_alpha[(size_t)ETOT * HH];   // CSR-ordered UNNORMALIZED p
__device__ float  g_pr[(size_t)NNODES * 128];   // scorer P|R per node
__device__ float  g_Wt1[256 * 128];             // W1^T  [256][128]
__device__ float  g_Wt2[256 * 256];             // W2^T  [256][256]
__device__ float  g_Wts[128 * 256];             // [Ws1_top|Ws1_bot]^T [128][256]

// ============================ helpers =======================================
__device__ __forceinline__ uint32_t f2tf32(float x) {
    uint32_t u;
    asm("cvt.rna.tf32.f32 %0, %1;" : "=r"(u) : "f"(x));
    return u;
}

__device__ __forceinline__ void mma1688(float& c0, float& c1, float& c2, float& c3,
                                        uint32_t a0, uint32_t a1, uint32_t a2, uint32_t a3,
                                        uint32_t b0, uint32_t b1) {
    asm volatile(
        "mma.sync.aligned.m16n8k8.row.col.f32.tf32.tf32.f32 "
        "{%0,%1,%2,%3}, {%4,%5,%6,%7}, {%8,%9}, {%0,%1,%2,%3};"
        : "+f"(c0), "+f"(c1), "+f"(c2), "+f"(c3)
        : "r"(a0), "r"(a1), "r"(a2), "r"(a3), "r"(b0), "r"(b1));
}

// ---------------- init: zero hist + dtype detection --------------------------
__device__ __forceinline__ int check_is_i64(const long long* q) {
    int ok = 1;
#pragma unroll
    for (int i = 0; i < 8; i++) {
        long long v = q[i];
        if (v < 0 || v >= NNODES) ok = 0;
    }
    return ok;
}

__global__ void init_k(const void* ei, const void* eli) {
    int i = blockIdx.x * blockDim.x + threadIdx.x;
    if (i < NNODES) g_fill[i] = 0;
    if (i == 0) {
        g_flag64_e = check_is_i64((const long long*)ei);
        g_flag64_l = check_is_i64((const long long*)eli);
    }
}

// ---------------- edge conversion + self loops + histogram ------------------
__global__ void build_edges(const void* ei) {
    int i = blockIdx.x * blockDim.x + threadIdx.x;
    if (i >= ETOT) return;
    int s, d;
    if (i < NEDGES) {
        if (g_flag64_e) {
            const long long* q = (const long long*)ei;
            s = (int)q[i]; d = (int)q[NEDGES + i];
        } else {
            const int* q = (const int*)ei;
            s = q[i]; d = q[NEDGES + i];
        }
    } else {
        s = i - NEDGES; d = s;   // self loop
    }
    g_esrc[i] = s; g_edst[i] = d;
    atomicAdd(&g_fill[d], 1);
}

__global__ void build_labels(const void* eli) {
    int i = blockIdx.x * blockDim.x + threadIdx.x;
    if (i >= NLBL) return;
    if (g_flag64_l) {
        const long long* q = (const long long*)eli;
        g_lu[i] = (int)q[i]; g_lv[i] = (int)q[NLBL + i];
    } else {
        const int* q = (const int*)eli;
        g_lu[i] = q[i]; g_lv[i] = q[NLBL + i];
    }
}

// ---------------- CSR build: hierarchical scan -------------------------------
__global__ void scan1_k() {
    __shared__ int sh[256];
    int t = threadIdx.x;
    int i = blockIdx.x * 256 + t;
    int v = (i < NNODES) ? g_fill[i] : 0;
    sh[t] = v; __syncthreads();
    for (int o = 1; o < 256; o <<= 1) {
        int a = (t >= o) ? sh[t - o] : 0;
        __syncthreads();
        sh[t] += a;
        __syncthreads();
    }
    if (i < NNODES) g_incl[i] = sh[t];
    if (t == 255) g_bsum[blockIdx.x] = sh[255];
}

__global__ void scan2_k(int nb) {
    __shared__ int sh[256];
    int t = threadIdx.x;
    int v = (t < nb) ? g_bsum[t] : 0;
    sh[t] = v; __syncthreads();
    for (int o = 1; o < 256; o <<= 1) {
        int a = (t >= o) ? sh[t - o] : 0;
        __syncthreads();
        sh[t] += a;
        __syncthreads();
    }
    if (t < nb) g_bsum[t] = sh[t] - v;   // exclusive
}

__global__ void scan3_k() {
    int i = blockIdx.x * blockDim.x + threadIdx.x;
    if (i >= NNODES) return;
    int tot = g_bsum[i >> 8] + g_incl[i];
    int orig = g_fill[i];
    g_rowptr[i + 1] = tot;
    g_fill[i] = tot - orig;              // exclusive offsets for scatter
    if (i == 0) g_rowptr[0] = 0;
}

__global__ void scatter_k() {
    int i = blockIdx.x * blockDim.x + threadIdx.x;
    if (i >= ETOT) return;
    int pos = atomicAdd(&g_fill[g_edst[i]], 1);
    g_csr_src[pos] = g_esrc[i];
}

// ---------------- weight prep (all transposes in one kernel) ----------------
__global__ void prep_weights_k(const float* __restrict__ W1,
                               const float* __restrict__ W2,
                               const float* __restrict__ Ws1) {
    int i = blockIdx.x * blockDim.x + threadIdx.x;
    if (i < 256 * 128) {
        int n = i >> 7, k = i & 127;
        g_Wt1[i] = W1[k * 256 + n];
    }
    int j = i - 256 * 128;
    if (j >= 0 && j < 256 * 256) {
        int n = j >> 8, k = j & 255;
        g_Wt2[j] = W2[k * 256 + n];
    }
    int l = i - 256 * 128 - 256 * 256;
    if (l >= 0 && l < 128 * 256) {
        int n = l >> 8, k = l & 255;
        g_Wts[l] = (n < 64) ? Ws1[k * 64 + n] : Ws1[(256 + k) * 64 + (n - 64)];
    }
}

// ---------------- tf32 mma.sync GEMM with register prefetch -----------------
// C[M,NTR] = A[M,KDIM] @ Bt[NTR,KDIM]^T   (Bt row-major, K contiguous)
// Block tile 128x64, 8 warps (4 in M x 2 in N), warp tile 32x32.
// LOGITS: fused head logits (64-col block == one head). OUTH: write half2 C.
template <int KDIM, int NTR, bool LOGITS, bool OUTH>
__global__ void __launch_bounds__(256) gemm_mma(
    const float* __restrict__ A, const float* __restrict__ Bt,
    void* __restrict__ Cv, int M,
    const float* __restrict__ a_src, const float* __restrict__ a_dst,
    float* __restrict__ als, float* __restrict__ ald)
{
    __shared__ uint32_t As[128 * 36];
    __shared__ uint32_t Bs[64 * 36];
    __shared__ float red[4][128];

    int tid = threadIdx.x;
    int wid = tid >> 5, lane = tid & 31;
    int warp_m = wid & 3, warp_n = wid >> 2;
    int g = lane >> 2, t = lane & 3;

    int rowBase = blockIdx.y * 128;
    int colBase = blockIdx.x * 64;

    float c[2][4][4];
#pragma unroll
    for (int i = 0; i < 2; i++)
#pragma unroll
        for (int j = 0; j < 4; j++)
#pragma unroll
            for (int k = 0; k < 4; k++) c[i][j][k] = 0.f;

    constexpr int NC = KDIM / 32;
    float4 ra[4], rb[2];
    {
#pragma unroll
        for (int j = 0; j < 4; j++) {
            int idx = tid + 256 * j;
            int r = idx >> 3, q = idx & 7;
            int gr = rowBase + r;
            ra[j] = (gr < M) ? *(const float4*)(A + (size_t)gr * KDIM + q * 4)
                             : make_float4(0.f, 0.f, 0.f, 0.f);
        }
#pragma unroll
        for (int j = 0; j < 2; j++) {
            int idx = tid + 256 * j;
            int r = idx >> 3, q = idx & 7;
            rb[j] = *(const float4*)(Bt + (size_t)(colBase + r) * KDIM + q * 4);
        }
    }

    for (int kc = 0; kc < NC; kc++) {
#pragma unroll
        for (int j = 0; j < 4; j++) {
            int idx = tid + 256 * j;
            int r = idx >> 3, q = idx & 7;
            uint4 u = { f2tf32(ra[j].x), f2tf32(ra[j].y), f2tf32(ra[j].z), f2tf32(ra[j].w) };
            *(uint4*)&As[r * 36 + q * 4] = u;
        }
#pragma unroll
        for (int j = 0; j < 2; j++) {
            int idx = tid + 256 * j;
            int r = idx >> 3, q = idx & 7;
            uint4 u = { f2tf32(rb[j].x), f2tf32(rb[j].y), f2tf32(rb[j].z), f2tf32(rb[j].w) };
            *(uint4*)&Bs[r * 36 + q * 4] = u;
        }
        __syncthreads();

        if (kc + 1 < NC) {
            int k0 = (kc + 1) * 32;
#pragma unroll
            for (int j = 0; j < 4; j++) {
                int idx = tid + 256 * j;
                int r = idx >> 3, q = idx & 7;
                int gr = rowBase + r;
                ra[j] = (gr < M) ? *(const float4*)(A + (size_t)gr * KDIM + k0 + q * 4)
                                 : make_float4(0.f, 0.f, 0.f, 0.f);
            }
#pragma unroll
            for (int j = 0; j < 2; j++) {
                int idx = tid + 256 * j;
                int r = idx >> 3, q = idx & 7;
                rb[j] = *(const float4*)(Bt + (size_t)(colBase + r) * KDIM + k0 + q * 4);
            }
        }

#pragma unroll
        for (int ks = 0; ks < 4; ks++) {
            int kk = ks * 8;
            uint32_t a[2][4];
#pragma unroll
            for (int tm = 0; tm < 2; tm++) {
                int r0 = warp_m * 32 + tm * 16;
                a[tm][0] = As[(r0 + g) * 36 + kk + t];
                a[tm][1] = As[(r0 + g + 8) * 36 + kk + t];
                a[tm][2] = As[(r0 + g) * 36 + kk + t + 4];
                a[tm][3] = As[(r0 + g + 8) * 36 + kk + t + 4];
            }
            uint32_t b[4][2];
#pragma unroll
            for (int tn = 0; tn < 4; tn++) {
                int n0 = warp_n * 32 + tn * 8 + g;
                b[tn][0] = Bs[n0 * 36 + kk + t];
                b[tn][1] = Bs[n0 * 36 + kk + t + 4];
            }
#pragma unroll
            for (int tm = 0; tm < 2; tm++)
#pragma unroll
                for (int tn = 0; tn < 4; tn++)
                    mma1688(c[tm][tn][0], c[tm][tn][1], c[tm][tn][2], c[tm][tn][3],
                            a[tm][0], a[tm][1], a[tm][2], a[tm][3],
                            b[tn][0], b[tn][1]);
        }
        __syncthreads();
    }

    // epilogue: store C (+ fused logits)
    float ps[2][2], pd[2][2];
    if (LOGITS) {
#pragma unroll
        for (int tm = 0; tm < 2; tm++)
            ps[tm][0] = ps[tm][1] = pd[tm][0] = pd[tm][1] = 0.f;
    }
#pragma unroll
    for (int tm = 0; tm < 2; tm++) {
        int r0 = rowBase + warp_m * 32 + tm * 16 + g;
        int r1 = r0 + 8;
#pragma unroll
        for (int tn = 0; tn < 4; tn++) {
            int col = colBase + warp_n * 32 + tn * 8 + t * 2;
            if (LOGITS) {
                float s0 = a_src[col], s1 = a_src[col + 1];
                float d0 = a_dst[col], d1 = a_dst[col + 1];
                ps[tm][0] += c[tm][tn][0] * s0 + c[tm][tn][1] * s1;
                pd[tm][0] += c[tm][tn][0] * d0 + c[tm][tn][1] * d1;
                ps[tm][1] += c[tm][tn][2] * s0 + c[tm][tn][3] * s1;
                pd[tm][1] += c[tm][tn][2] * d0 + c[tm][tn][3] * d1;
            }
            if (OUTH) {
                __half* C = (__half*)Cv;
                if (r0 < M)
                    *(__half2*)(C + (size_t)r0 * NTR + col) =
                        __floats2half2_rn(c[tm][tn][0], c[tm][tn][1]);
                if (r1 < M)
                    *(__half2*)(C + (size_t)r1 * NTR + col) =
                        __floats2half2_rn(c[tm][tn][2], c[tm][tn][3]);
            } else {
                float* C = (float*)Cv;
                if (r0 < M)
                    *(float2*)(C + (size_t)r0 * NTR + col) = make_float2(c[tm][tn][0], c[tm][tn][1]);
                if (r1 < M)
                    *(float2*)(C + (size_t)r1 * NTR + col) = make_float2(c[tm][tn][2], c[tm][tn][3]);
            }
        }
    }
    if (LOGITS) {
#pragma unroll
        for (int tm = 0; tm < 2; tm++)
#pragma unroll
            for (int rr = 0; rr < 2; rr++) {
#pragma unroll
                for (int o = 1; o < 4; o <<= 1) {
                    ps[tm][rr] += __shfl_xor_sync(0xffffffffu, ps[tm][rr], o);
                    pd[tm][rr] += __shfl_xor_sync(0xffffffffu, pd[tm][rr], o);
                }
            }
        __syncthreads();
        if (t == 0) {
#pragma unroll
            for (int tm = 0; tm < 2; tm++) {
                int rl = warp_m * 32 + tm * 16 + g;
                red[warp_n * 2 + 0][rl]     = ps[tm][0];
                red[warp_n * 2 + 0][rl + 8] = ps[tm][1];
                red[warp_n * 2 + 1][rl]     = pd[tm][0];
                red[warp_n * 2 + 1][rl + 8] = pd[tm][1];
            }
        }
        __syncthreads();
        if (tid < 128) {
            int row = rowBase + tid;
            if (row < M) {
                int h = blockIdx.x;   // 64-col block == one head
                als[row * 4 + h] = red[0][tid] + red[2][tid];
                ald[row * 4 + h] = red[1][tid] + red[3][tid];
            }
        }
    }
}

// ---------------- per-node softmax (2 passes, unnormalized p + inv denom) ---
__global__ void attn_softmax_k() {
    int node = (blockIdx.x * blockDim.x + threadIdx.x) >> 5;
    int lane = threadIdx.x & 31;
    if (node >= NNODES) return;
    int beg = g_rowptr[node], end = g_rowptr[node + 1];

    float4 adv = *(const float4*)&g_ald[node * 4];
    float ad[4] = {adv.x, adv.y, adv.z, adv.w};

    float mx[4] = {-INFINITY, -INFINITY, -INFINITY, -INFINITY};
    for (int k = beg + lane; k < end; k += 32) {
        int s = g_csr_src[k];
        float4 av = *(const float4*)&g_als[s * 4];
        float e[4] = {av.x + ad[0], av.y + ad[1], av.z + ad[2], av.w + ad[3]};
#pragma unroll
        for (int h = 0; h < 4; h++) {
            float v = e[h] > 0.f ? e[h] : 0.2f * e[h];
            mx[h] = fmaxf(mx[h], v);
        }
    }
#pragma unroll
    for (int h = 0; h < 4; h++)
#pragma unroll
        for (int o = 16; o; o >>= 1)
            mx[h] = fmaxf(mx[h], __shfl_xor_sync(0xffffffffu, mx[h], o));

    float sm[4] = {0.f, 0.f, 0.f, 0.f};
    for (int k = beg + lane; k < end; k += 32) {
        int s = g_csr_src[k];
        float4 av = *(const float4*)&g_als[s * 4];
        float e[4] = {av.x + ad[0], av.y + ad[1], av.z + ad[2], av.w + ad[3]};
        float p[4];
#pragma unroll
        for (int h = 0; h < 4; h++) {
            float v = e[h] > 0.f ? e[h] : 0.2f * e[h];
            p[h] = __expf(v - mx[h]);
            sm[h] += p[h];
        }
        *(float4*)&g_alpha[(size_t)k * 4] = make_float4(p[0], p[1], p[2], p[3]);
    }
#pragma unroll
    for (int h = 0; h < 4; h++)
#pragma unroll
        for (int o = 16; o; o >>= 1)
            sm[h] += __shfl_xor_sync(0xffffffffu, sm[h], o);
    if (!lane)
        *(float4*)&g_inv[node * 4] = make_float4(1.f / sm[0], 1.f / sm[1],
                                                 1.f / sm[2], 1.f / sm[3]);
}

// ---------------- pull aggregation: warp/node, fp16 h, fp32 accum -----------
__global__ void __launch_bounds__(256) aggregate_k(const float* __restrict__ bias) {
    int warp = threadIdx.x >> 5, lane = threadIdx.x & 31;
    int n = blockIdx.x * 8 + warp;
    if (n >= NNODES) return;
    int hh = lane >> 3;                         // 8 channels per lane -> head
    int beg = g_rowptr[n], end = g_rowptr[n + 1];
    const __half* hb = g_hbuf;

    float acc[8] = {};
#pragma unroll 2
    for (int k = beg; k < end; k++) {
        int s = g_csr_src[k];
        float w = g_alpha[(size_t)k * 4 + hh];
        uint4 u = *(const uint4*)(hb + (size_t)s * 256 + lane * 8);
        const __half2* ph = (const __half2*)&u;
#pragma unroll
        for (int j = 0; j < 4; j++) {
            float2 f = __half22float2(ph[j]);
            acc[2 * j]     = fmaf(w, f.x, acc[2 * j]);
            acc[2 * j + 1] = fmaf(w, f.y, acc[2 * j + 1]);
        }
    }
    float inv = g_inv[n * 4 + hh];
    float4 b0 = *(const float4*)&bias[lane * 8];
    float4 b1 = *(const float4*)&bias[lane * 8 + 4];
    float o[8];
    o[0] = fmaf(acc[0], inv, b0.x); o[1] = fmaf(acc[1], inv, b0.y);
    o[2] = fmaf(acc[2], inv, b0.z); o[3] = fmaf(acc[3], inv, b0.w);
    o[4] = fmaf(acc[4], inv, b1.x); o[5] = fmaf(acc[5], inv, b1.y);
    o[6] = fmaf(acc[6], inv, b1.z); o[7] = fmaf(acc[7], inv, b1.w);
#pragma unroll
    for (int j = 0; j < 8; j++)
        o[j] = o[j] > 0.f ? o[j] : (__expf(o[j]) - 1.f);
    float* zp = g_zbuf + (size_t)n * 256 + lane * 8;
    *(float4*)zp       = make_float4(o[0], o[1], o[2], o[3]);
    *(float4*)(zp + 4) = make_float4(o[4], o[5], o[6], o[7]);
}

// ---------------- fused scorer: out = relu(P[u]+R[v]+bs1) . Ws2 + bs2 -------
__global__ void score_k(const float* __restrict__ bs1, const float* __restrict__ Ws2,
                        const float* __restrict__ bs2, float* __restrict__ out) {
    int e = (blockIdx.x * blockDim.x + threadIdx.x) >> 5;
    int lane = threadIdx.x & 31;
    if (e >= NLBL) return;
    int u = g_lu[e], v = g_lv[e];
    const float* pu = g_pr + (size_t)u * 128;
    const float* rv = g_pr + (size_t)v * 128 + 64;
    float s = 0.f;
#pragma unroll
    for (int j = 0; j < 2; j++) {
        int c = lane + j * 32;
        float h = pu[c] + rv[c] + bs1[c];
        h = fmaxf(h, 0.f);
        s = fmaf(h, Ws2[c], s);
    }
#pragma unroll
    for (int o = 16; o; o >>= 1) s += __shfl_xor_sync(0xffffffffu, s, o);
    if (!lane) out[e] = s + bs2[0];
}

// ---------------- launcher --------------------------------------------------
extern "C" void kernel_launch(void* const* d_in, const int* in_sizes, int n_in,
                              void* d_out, int out_size) {
    const float* x   = (const float*)d_in[0];
    const void*  ei  = d_in[1];
    const void*  eli = d_in[2];
    const float* W1  = (const float*)d_in[3];
    const float* as1 = (const float*)d_in[4];
    const float* ad1 = (const float*)d_in[5];
    const float* b1  = (const float*)d_in[6];
    const float* W2  = (const float*)d_in[7];
    const float* as2 = (const float*)d_in[8];
    const float* ad2 = (const float*)d_in[9];
    const float* b2  = (const float*)d_in[10];
    const float* Ws1 = (const float*)d_in[11];
    const float* bs1 = (const float*)d_in[12];
    const float* Ws2 = (const float*)d_in[13];
    const float* bs2 = (const float*)d_in[14];
    float* out = (float*)d_out;

    void *hptr;
    float *zptr, *prptr, *wt1, *wt2, *wts, *alsp, *aldp;
    cudaGetSymbolAddress(&hptr, g_hbuf);
    cudaGetSymbolAddress((void**)&zptr, g_zbuf);
    cudaGetSymbolAddress((void**)&prptr, g_pr);
    cudaGetSymbolAddress((void**)&wt1, g_Wt1);
    cudaGetSymbolAddress((void**)&wt2, g_Wt2);
    cudaGetSymbolAddress((void**)&wts, g_Wts);
    cudaGetSymbolAddress((void**)&alsp, g_als);
    cudaGetSymbolAddress((void**)&aldp, g_ald);

    // graph prep
    init_k<<<(NNODES + 255) / 256, 256>>>(ei, eli);
    build_edges<<<(ETOT + 255) / 256, 256>>>(ei);
    build_labels<<<(NLBL + 255) / 256, 256>>>(eli);
    int nb = (NNODES + 255) / 256;   // 196
    scan1_k<<<nb, 256>>>();
    scan2_k<<<1, 256>>>(nb);
    scan3_k<<<(NNODES + 255) / 256, 256>>>();
    scatter_k<<<(ETOT + 255) / 256, 256>>>();

    // weight prep (one kernel)
    int wtot = 256 * 128 + 256 * 256 + 128 * 256;
    prep_weights_k<<<(wtot + 255) / 256, 256>>>(W1, W2, Ws1);

    int mrows = (NNODES + 127) / 128;   // 391

    // ---- layer 1 ----
    gemm_mma<128, 256, true, true><<<dim3(4, mrows), 256>>>(x, wt1, hptr, NNODES,
                                                            as1, ad1, alsp, aldp);
    attn_softmax_k<<<(NNODES + 7) / 8, 256>>>();
    aggregate_k<<<(NNODES + 7) / 8, 256>>>(b1);

    // ---- layer 2 ----
    gemm_mma<256, 256, true, true><<<dim3(4, mrows), 256>>>(zptr, wt2, hptr, NNODES,
                                                            as2, ad2, alsp, aldp);
    attn_softmax_k<<<(NNODES + 7) / 8, 256>>>();
    aggregate_k<<<(NNODES + 7) / 8, 256>>>(b2);

    // ---- scorer ----
    gemm_mma<256, 128, false, false><<<dim3(2, mrows), 256>>>(zptr, wts, prptr, NNODES,
                                                              nullptr, nullptr, nullptr, nullptr);
    score_k<<<(NLBL + 7) / 8, 256>>>(bs1, Ws2, bs2, out);
}

// round 7
// speedup vs baseline: 3.2306x; 1.0521x over previous
#include <cuda_runtime.h>
#include <cuda_fp16.h>
#include <math.h>
#include <stdint.h>

#define NNODES 50000
#define NEDGES 800000
#define ETOT   (NEDGES + NNODES)
#define NLBL   100000
#define FIN    128
#define HH     4
#define CC     64
#define DD     256

// ---------------- scratch (device globals; no allocation allowed) ----------
__device__ int    g_flag64_e;
__device__ int    g_flag64_l;
__device__ int    g_rowptr[NNODES + 1];
__device__ int    g_fill[NNODES];
__device__ int    g_incl[NNODES];
__device__ int    g_bsum[256];
__device__ int    g_csr_src[ETOT];
__device__ int    g_esrc[ETOT];
__device__ int    g_edst[ETOT];
__device__ int    g_lu[NLBL];
__device__ int    g_lv[NLBL];
__device__ __half g_hbuf[(size_t)NNODES * DD];  // GEMM output (fp16) / agg input
__device__ float  g_zbuf[(size_t)NNODES * DD];  // agg output / next GEMM input
__device__ float  g_als[NNODES * HH];
__device__ float  g_ald[NNODES * HH];
__device__ float  g_inv[NNODES * HH];           // 1/softmax denom per node,head
__device__ float  g_alpha[(size_t)ETOT * HH];   // CSR-ordered UNNORMALIZED p
__device__ float  g_pr[(size_t)NNODES * 128];   // scorer P|R per node
__device__ float  g_Wt1[256 * 128];             // W1^T  [256][128]
__device__ float  g_Wt2[256 * 256];             // W2^T  [256][256]
__device__ float  g_Wts[128 * 256];             // [Ws1_top|Ws1_bot]^T [128][256]

// ============================ helpers =======================================
__device__ __forceinline__ uint32_t f2tf32(float x) {
    uint32_t u;
    asm("cvt.rna.tf32.f32 %0, %1;" : "=r"(u) : "f"(x));
    return u;
}

__device__ __forceinline__ void mma1688(float& c0, float& c1, float& c2, float& c3,
                                        uint32_t a0, uint32_t a1, uint32_t a2, uint32_t a3,
                                        uint32_t b0, uint32_t b1) {
    asm volatile(
        "mma.sync.aligned.m16n8k8.row.col.f32.tf32.tf32.f32 "
        "{%0,%1,%2,%3}, {%4,%5,%6,%7}, {%8,%9}, {%0,%1,%2,%3};"
        : "+f"(c0), "+f"(c1), "+f"(c2), "+f"(c3)
        : "r"(a0), "r"(a1), "r"(a2), "r"(a3), "r"(b0), "r"(b1));
}

// ---------------- init: zero hist + dtype detection --------------------------
__device__ __forceinline__ int check_is_i64(const long long* q) {
    int ok = 1;
#pragma unroll
    for (int i = 0; i < 8; i++) {
        long long v = q[i];
        if (v < 0 || v >= NNODES) ok = 0;
    }
    return ok;
}

__global__ void init_k(const void* ei, const void* eli) {
    int i = blockIdx.x * blockDim.x + threadIdx.x;
    if (i < NNODES) g_fill[i] = 0;
    if (i == 0) {
        g_flag64_e = check_is_i64((const long long*)ei);
        g_flag64_l = check_is_i64((const long long*)eli);
    }
}

// ---------------- edge conversion + self loops + histogram ------------------
__global__ void build_edges(const void* ei) {
    int i = blockIdx.x * blockDim.x + threadIdx.x;
    if (i >= ETOT) return;
    int s, d;
    if (i < NEDGES) {
        if (g_flag64_e) {
            const long long* q = (const long long*)ei;
            s = (int)q[i]; d = (int)q[NEDGES + i];
        } else {
            const int* q = (const int*)ei;
            s = q[i]; d = q[NEDGES + i];
        }
    } else {
        s = i - NEDGES; d = s;   // self loop
    }
    g_esrc[i] = s; g_edst[i] = d;
    atomicAdd(&g_fill[d], 1);
}

__global__ void build_labels(const void* eli) {
    int i = blockIdx.x * blockDim.x + threadIdx.x;
    if (i >= NLBL) return;
    if (g_flag64_l) {
        const long long* q = (const long long*)eli;
        g_lu[i] = (int)q[i]; g_lv[i] = (int)q[NLBL + i];
    } else {
        const int* q = (const int*)eli;
        g_lu[i] = q[i]; g_lv[i] = q[NLBL + i];
    }
}

// ---------------- CSR build: hierarchical scan -------------------------------
__global__ void scan1_k() {
    __shared__ int sh[256];
    int t = threadIdx.x;
    int i = blockIdx.x * 256 + t;
    int v = (i < NNODES) ? g_fill[i] : 0;
    sh[t] = v; __syncthreads();
    for (int o = 1; o < 256; o <<= 1) {
        int a = (t >= o) ? sh[t - o] : 0;
        __syncthreads();
        sh[t] += a;
        __syncthreads();
    }
    if (i < NNODES) g_incl[i] = sh[t];
    if (t == 255) g_bsum[blockIdx.x] = sh[255];
}

__global__ void scan2_k(int nb) {
    __shared__ int sh[256];
    int t = threadIdx.x;
    int v = (t < nb) ? g_bsum[t] : 0;
    sh[t] = v; __syncthreads();
    for (int o = 1; o < 256; o <<= 1) {
        int a = (t >= o) ? sh[t - o] : 0;
        __syncthreads();
        sh[t] += a;
        __syncthreads();
    }
    if (t < nb) g_bsum[t] = sh[t] - v;   // exclusive
}

__global__ void scan3_k() {
    int i = blockIdx.x * blockDim.x + threadIdx.x;
    if (i >= NNODES) return;
    int tot = g_bsum[i >> 8] + g_incl[i];
    int orig = g_fill[i];
    g_rowptr[i + 1] = tot;
    g_fill[i] = tot - orig;              // exclusive offsets for scatter
    if (i == 0) g_rowptr[0] = 0;
}

__global__ void scatter_k() {
    int i = blockIdx.x * blockDim.x + threadIdx.x;
    if (i >= ETOT) return;
    int pos = atomicAdd(&g_fill[g_edst[i]], 1);
    g_csr_src[pos] = g_esrc[i];
}

// ---------------- weight prep (all transposes in one kernel) ----------------
__global__ void prep_weights_k(const float* __restrict__ W1,
                               const float* __restrict__ W2,
                               const float* __restrict__ Ws1) {
    int i = blockIdx.x * blockDim.x + threadIdx.x;
    if (i < 256 * 128) {
        int n = i >> 7, k = i & 127;
        g_Wt1[i] = W1[k * 256 + n];
    }
    int j = i - 256 * 128;
    if (j >= 0 && j < 256 * 256) {
        int n = j >> 8, k = j & 255;
        g_Wt2[j] = W2[k * 256 + n];
    }
    int l = i - 256 * 128 - 256 * 256;
    if (l >= 0 && l < 128 * 256) {
        int n = l >> 8, k = l & 255;
        g_Wts[l] = (n < 64) ? Ws1[k * 64 + n] : Ws1[(256 + k) * 64 + (n - 64)];
    }
}

// ---------------- tf32 mma.sync GEMM with register prefetch -----------------
// C[M,NTR] = A[M,KDIM] @ Bt[NTR,KDIM]^T   (Bt row-major, K contiguous)
// Block tile 128x64, 8 warps (4 in M x 2 in N), warp tile 32x32.
// LOGITS: fused head logits (64-col block == one head). OUTH: write half2 C.
template <int KDIM, int NTR, bool LOGITS, bool OUTH>
__global__ void __launch_bounds__(256) gemm_mma(
    const float* __restrict__ A, const float* __restrict__ Bt,
    void* __restrict__ Cv, int M,
    const float* __restrict__ a_src, const float* __restrict__ a_dst,
    float* __restrict__ als, float* __restrict__ ald)
{
    __shared__ uint32_t As[128 * 36];
    __shared__ uint32_t Bs[64 * 36];
    __shared__ float red[4][128];

    int tid = threadIdx.x;
    int wid = tid >> 5, lane = tid & 31;
    int warp_m = wid & 3, warp_n = wid >> 2;
    int g = lane >> 2, t = lane & 3;

    int rowBase = blockIdx.y * 128;
    int colBase = blockIdx.x * 64;

    float c[2][4][4];
#pragma unroll
    for (int i = 0; i < 2; i++)
#pragma unroll
        for (int j = 0; j < 4; j++)
#pragma unroll
            for (int k = 0; k < 4; k++) c[i][j][k] = 0.f;

    constexpr int NC = KDIM / 32;
    float4 ra[4], rb[2];
    {
#pragma unroll
        for (int j = 0; j < 4; j++) {
            int idx = tid + 256 * j;
            int r = idx >> 3, q = idx & 7;
            int gr = rowBase + r;
            ra[j] = (gr < M) ? *(const float4*)(A + (size_t)gr * KDIM + q * 4)
                             : make_float4(0.f, 0.f, 0.f, 0.f);
        }
#pragma unroll
        for (int j = 0; j < 2; j++) {
            int idx = tid + 256 * j;
            int r = idx >> 3, q = idx & 7;
            rb[j] = *(const float4*)(Bt + (size_t)(colBase + r) * KDIM + q * 4);
        }
    }

    for (int kc = 0; kc < NC; kc++) {
#pragma unroll
        for (int j = 0; j < 4; j++) {
            int idx = tid + 256 * j;
            int r = idx >> 3, q = idx & 7;
            uint4 u = { f2tf32(ra[j].x), f2tf32(ra[j].y), f2tf32(ra[j].z), f2tf32(ra[j].w) };
            *(uint4*)&As[r * 36 + q * 4] = u;
        }
#pragma unroll
        for (int j = 0; j < 2; j++) {
            int idx = tid + 256 * j;
            int r = idx >> 3, q = idx & 7;
            uint4 u = { f2tf32(rb[j].x), f2tf32(rb[j].y), f2tf32(rb[j].z), f2tf32(rb[j].w) };
            *(uint4*)&Bs[r * 36 + q * 4] = u;
        }
        __syncthreads();

        if (kc + 1 < NC) {
            int k0 = (kc + 1) * 32;
#pragma unroll
            for (int j = 0; j < 4; j++) {
                int idx = tid + 256 * j;
                int r = idx >> 3, q = idx & 7;
                int gr = rowBase + r;
                ra[j] = (gr < M) ? *(const float4*)(A + (size_t)gr * KDIM + k0 + q * 4)
                                 : make_float4(0.f, 0.f, 0.f, 0.f);
            }
#pragma unroll
            for (int j = 0; j < 2; j++) {
                int idx = tid + 256 * j;
                int r = idx >> 3, q = idx & 7;
                rb[j] = *(const float4*)(Bt + (size_t)(colBase + r) * KDIM + k0 + q * 4);
            }
        }

#pragma unroll
        for (int ks = 0; ks < 4; ks++) {
            int kk = ks * 8;
            uint32_t a[2][4];
#pragma unroll
            for (int tm = 0; tm < 2; tm++) {
                int r0 = warp_m * 32 + tm * 16;
                a[tm][0] = As[(r0 + g) * 36 + kk + t];
                a[tm][1] = As[(r0 + g + 8) * 36 + kk + t];
                a[tm][2] = As[(r0 + g) * 36 + kk + t + 4];
                a[tm][3] = As[(r0 + g + 8) * 36 + kk + t + 4];
            }
            uint32_t b[4][2];
#pragma unroll
            for (int tn = 0; tn < 4; tn++) {
                int n0 = warp_n * 32 + tn * 8 + g;
                b[tn][0] = Bs[n0 * 36 + kk + t];
                b[tn][1] = Bs[n0 * 36 + kk + t + 4];
            }
#pragma unroll
            for (int tm = 0; tm < 2; tm++)
#pragma unroll
                for (int tn = 0; tn < 4; tn++)
                    mma1688(c[tm][tn][0], c[tm][tn][1], c[tm][tn][2], c[tm][tn][3],
                            a[tm][0], a[tm][1], a[tm][2], a[tm][3],
                            b[tn][0], b[tn][1]);
        }
        __syncthreads();
    }

    // epilogue: store C (+ fused logits)
    float ps[2][2], pd[2][2];
    if (LOGITS) {
#pragma unroll
        for (int tm = 0; tm < 2; tm++)
            ps[tm][0] = ps[tm][1] = pd[tm][0] = pd[tm][1] = 0.f;
    }
#pragma unroll
    for (int tm = 0; tm < 2; tm++) {
        int r0 = rowBase + warp_m * 32 + tm * 16 + g;
        int r1 = r0 + 8;
#pragma unroll
        for (int tn = 0; tn < 4; tn++) {
            int col = colBase + warp_n * 32 + tn * 8 + t * 2;
            if (LOGITS) {
                float s0 = a_src[col], s1 = a_src[col + 1];
                float d0 = a_dst[col], d1 = a_dst[col + 1];
                ps[tm][0] += c[tm][tn][0] * s0 + c[tm][tn][1] * s1;
                pd[tm][0] += c[tm][tn][0] * d0 + c[tm][tn][1] * d1;
                ps[tm][1] += c[tm][tn][2] * s0 + c[tm][tn][3] * s1;
                pd[tm][1] += c[tm][tn][2] * d0 + c[tm][tn][3] * d1;
            }
            if (OUTH) {
                __half* C = (__half*)Cv;
                if (r0 < M)
                    *(__half2*)(C + (size_t)r0 * NTR + col) =
                        __floats2half2_rn(c[tm][tn][0], c[tm][tn][1]);
                if (r1 < M)
                    *(__half2*)(C + (size_t)r1 * NTR + col) =
                        __floats2half2_rn(c[tm][tn][2], c[tm][tn][3]);
            } else {
                float* C = (float*)Cv;
                if (r0 < M)
                    *(float2*)(C + (size_t)r0 * NTR + col) = make_float2(c[tm][tn][0], c[tm][tn][1]);
                if (r1 < M)
                    *(float2*)(C + (size_t)r1 * NTR + col) = make_float2(c[tm][tn][2], c[tm][tn][3]);
            }
        }
    }
    if (LOGITS) {
#pragma unroll
        for (int tm = 0; tm < 2; tm++)
#pragma unroll
            for (int rr = 0; rr < 2; rr++) {
#pragma unroll
                for (int o = 1; o < 4; o <<= 1) {
                    ps[tm][rr] += __shfl_xor_sync(0xffffffffu, ps[tm][rr], o);
                    pd[tm][rr] += __shfl_xor_sync(0xffffffffu, pd[tm][rr], o);
                }
            }
        __syncthreads();
        if (t == 0) {
#pragma unroll
            for (int tm = 0; tm < 2; tm++) {
                int rl = warp_m * 32 + tm * 16 + g;
                red[warp_n * 2 + 0][rl]     = ps[tm][0];
                red[warp_n * 2 + 0][rl + 8] = ps[tm][1];
                red[warp_n * 2 + 1][rl]     = pd[tm][0];
                red[warp_n * 2 + 1][rl + 8] = pd[tm][1];
            }
        }
        __syncthreads();
        if (tid < 128) {
            int row = rowBase + tid;
            if (row < M) {
                int h = blockIdx.x;   // 64-col block == one head
                als[row * 4 + h] = red[0][tid] + red[2][tid];
                ald[row * 4 + h] = red[1][tid] + red[3][tid];
            }
        }
    }
}

// ---------------- per-node softmax: ONE pass (logits are O(1), no max) ------
__global__ void attn_softmax_k() {
    int node = (blockIdx.x * blockDim.x + threadIdx.x) >> 5;
    int lane = threadIdx.x & 31;
    if (node >= NNODES) return;
    int beg = g_rowptr[node], end = g_rowptr[node + 1];

    float4 adv = *(const float4*)&g_ald[node * 4];
    float ad[4] = {adv.x, adv.y, adv.z, adv.w};

    float sm[4] = {0.f, 0.f, 0.f, 0.f};
    for (int k = beg + lane; k < end; k += 32) {
        int s = g_csr_src[k];
        float4 av = *(const float4*)&g_als[s * 4];
        float e[4] = {av.x + ad[0], av.y + ad[1], av.z + ad[2], av.w + ad[3]};
        float p[4];
#pragma unroll
        for (int h = 0; h < 4; h++) {
            float v = e[h] > 0.f ? e[h] : 0.2f * e[h];
            p[h] = __expf(v);
            sm[h] += p[h];
        }
        *(float4*)&g_alpha[(size_t)k * 4] = make_float4(p[0], p[1], p[2], p[3]);
    }
#pragma unroll
    for (int h = 0; h < 4; h++)
#pragma unroll
        for (int o = 16; o; o >>= 1)
            sm[h] += __shfl_xor_sync(0xffffffffu, sm[h], o);
    if (!lane)
        *(float4*)&g_inv[node * 4] = make_float4(1.f / sm[0], 1.f / sm[1],
                                                 1.f / sm[2], 1.f / sm[3]);
}

// ---------------- pull aggregation: warp/node, fp16 h, fp32 accum -----------
__global__ void __launch_bounds__(256) aggregate_k(const float* __restrict__ bias) {
    int warp = threadIdx.x >> 5, lane = threadIdx.x & 31;
    int n = blockIdx.x * 8 + warp;
    if (n >= NNODES) return;
    int hh = lane >> 3;                         // 8 channels per lane -> head
    int beg = g_rowptr[n], end = g_rowptr[n + 1];
    const __half* hb = g_hbuf;

    float acc[8] = {};
#pragma unroll 2
    for (int k = beg; k < end; k++) {
        int s = g_csr_src[k];
        float w = g_alpha[(size_t)k * 4 + hh];
        uint4 u = *(const uint4*)(hb + (size_t)s * 256 + lane * 8);
        const __half2* ph = (const __half2*)&u;
#pragma unroll
        for (int j = 0; j < 4; j++) {
            float2 f = __half22float2(ph[j]);
            acc[2 * j]     = fmaf(w, f.x, acc[2 * j]);
            acc[2 * j + 1] = fmaf(w, f.y, acc[2 * j + 1]);
        }
    }
    float inv = g_inv[n * 4 + hh];
    float4 b0 = *(const float4*)&bias[lane * 8];
    float4 b1 = *(const float4*)&bias[lane * 8 + 4];
    float o[8];
    o[0] = fmaf(acc[0], inv, b0.x); o[1] = fmaf(acc[1], inv, b0.y);
    o[2] = fmaf(acc[2], inv, b0.z); o[3] = fmaf(acc[3], inv, b0.w);
    o[4] = fmaf(acc[4], inv, b1.x); o[5] = fmaf(acc[5], inv, b1.y);
    o[6] = fmaf(acc[6], inv, b1.z); o[7] = fmaf(acc[7], inv, b1.w);
#pragma unroll
    for (int j = 0; j < 8; j++)
        o[j] = o[j] > 0.f ? o[j] : (__expf(o[j]) - 1.f);
    float* zp = g_zbuf + (size_t)n * 256 + lane * 8;
    *(float4*)zp       = make_float4(o[0], o[1], o[2], o[3]);
    *(float4*)(zp + 4) = make_float4(o[4], o[5], o[6], o[7]);
}

// ---------------- fused scorer: out = relu(P[u]+R[v]+bs1) . Ws2 + bs2 -------
__global__ void score_k(const float* __restrict__ bs1, const float* __restrict__ Ws2,
                        const float* __restrict__ bs2, float* __restrict__ out) {
    int e = (blockIdx.x * blockDim.x + threadIdx.x) >> 5;
    int lane = threadIdx.x & 31;
    if (e >= NLBL) return;
    int u = g_lu[e], v = g_lv[e];
    const float* pu = g_pr + (size_t)u * 128;
    const float* rv = g_pr + (size_t)v * 128 + 64;
    float s = 0.f;
#pragma unroll
    for (int j = 0; j < 2; j++) {
        int c = lane + j * 32;
        float h = pu[c] + rv[c] + bs1[c];
        h = fmaxf(h, 0.f);
        s = fmaf(h, Ws2[c], s);
    }
#pragma unroll
    for (int o = 16; o; o >>= 1) s += __shfl_xor_sync(0xffffffffu, s, o);
    if (!lane) out[e] = s + bs2[0];
}

// ---------------- launcher --------------------------------------------------
extern "C" void kernel_launch(void* const* d_in, const int* in_sizes, int n_in,
                              void* d_out, int out_size) {
    const float* x   = (const float*)d_in[0];
    const void*  ei  = d_in[1];
    const void*  eli = d_in[2];
    const float* W1  = (const float*)d_in[3];
    const float* as1 = (const float*)d_in[4];
    const float* ad1 = (const float*)d_in[5];
    const float* b1  = (const float*)d_in[6];
    const float* W2  = (const float*)d_in[7];
    const float* as2 = (const float*)d_in[8];
    const float* ad2 = (const float*)d_in[9];
    const float* b2  = (const float*)d_in[10];
    const float* Ws1 = (const float*)d_in[11];
    const float* bs1 = (const float*)d_in[12];
    const float* Ws2 = (const float*)d_in[13];
    const float* bs2 = (const float*)d_in[14];
    float* out = (float*)d_out;

    void *hptr;
    float *zptr, *prptr, *wt1, *wt2, *wts, *alsp, *aldp;
    cudaGetSymbolAddress(&hptr, g_hbuf);
    cudaGetSymbolAddress((void**)&zptr, g_zbuf);
    cudaGetSymbolAddress((void**)&prptr, g_pr);
    cudaGetSymbolAddress((void**)&wt1, g_Wt1);
    cudaGetSymbolAddress((void**)&wt2, g_Wt2);
    cudaGetSymbolAddress((void**)&wts, g_Wts);
    cudaGetSymbolAddress((void**)&alsp, g_als);
    cudaGetSymbolAddress((void**)&aldp, g_ald);

    // side stream + fork/join events (created once, on the non-capture
    // correctness call; host-side only, no device memory involved)
    static cudaStream_t s2 = nullptr;
    static cudaEvent_t evFork = nullptr, evJoin = nullptr;
    if (!s2) {
        cudaStreamCreateWithFlags(&s2, cudaStreamNonBlocking);
        cudaEventCreateWithFlags(&evFork, cudaEventDisableTiming);
        cudaEventCreateWithFlags(&evJoin, cudaEventDisableTiming);
    }

    // fork: CSR build chain on s2, concurrent with weight prep + GEMM1
    cudaEventRecord(evFork, 0);
    cudaStreamWaitEvent(s2, evFork, 0);

    init_k<<<(NNODES + 255) / 256, 256, 0, s2>>>(ei, eli);
    build_edges<<<(ETOT + 255) / 256, 256, 0, s2>>>(ei);
    build_labels<<<(NLBL + 255) / 256, 256, 0, s2>>>(eli);
    int nb = (NNODES + 255) / 256;   // 196
    scan1_k<<<nb, 256, 0, s2>>>();
    scan2_k<<<1, 256, 0, s2>>>(nb);
    scan3_k<<<(NNODES + 255) / 256, 256, 0, s2>>>();
    scatter_k<<<(ETOT + 255) / 256, 256, 0, s2>>>();
    cudaEventRecord(evJoin, s2);

    // main stream: weight prep + layer-1 GEMM (independent of CSR)
    int wtot = 256 * 128 + 256 * 256 + 128 * 256;
    prep_weights_k<<<(wtot + 255) / 256, 256>>>(W1, W2, Ws1);

    int mrows = (NNODES + 127) / 128;   // 391
    gemm_mma<128, 256, true, true><<<dim3(4, mrows), 256>>>(x, wt1, hptr, NNODES,
                                                            as1, ad1, alsp, aldp);

    // join: softmax needs both CSR and logits
    cudaStreamWaitEvent(0, evJoin, 0);

    // ---- layer 1 edge pipeline ----
    attn_softmax_k<<<(NNODES + 7) / 8, 256>>>();
    aggregate_k<<<(NNODES + 7) / 8, 256>>>(b1);

    // ---- layer 2 ----
    gemm_mma<256, 256, true, true><<<dim3(4, mrows), 256>>>(zptr, wt2, hptr, NNODES,
                                                            as2, ad2, alsp, aldp);
    attn_softmax_k<<<(NNODES + 7) / 8, 256>>>();
    aggregate_k<<<(NNODES + 7) / 8, 256>>>(b2);

    // ---- scorer ----
    gemm_mma<256, 128, false, false><<<dim3(2, mrows), 256>>>(zptr, wts, prptr, NNODES,
                                                              nullptr, nullptr, nullptr, nullptr);
    score_k<<<(NLBL + 7) / 8, 256>>>(bs1, Ws2, bs2, out);
}

// round 8
// speedup vs baseline: 3.8792x; 1.2008x over previous
#include <cuda_runtime.h>
#include <cuda_fp16.h>
#include <math.h>
#include <stdint.h>

#define NNODES 50000
#define NEDGES 800000
#define ETOT   (NEDGES + NNODES)
#define NLBL   100000
#define FIN    128
#define HH     4
#define CC     64
#define DD     256

// ---------------- scratch (device globals; no allocation allowed) ----------
__device__ int    g_flag64_e;
__device__ int    g_flag64_l;
__device__ int    g_rowptr[NNODES + 1];
__device__ int    g_fill[NNODES];
__device__ int    g_incl[NNODES];
__device__ int    g_bsum[256];
__device__ int    g_csr_src[ETOT];
__device__ int    g_esrc[ETOT];
__device__ int    g_edst[ETOT];
__device__ int    g_lu[NLBL];
__device__ int    g_lv[NLBL];
__device__ __half g_hbuf[(size_t)NNODES * DD];  // GEMM output (fp16) / agg input
__device__ float  g_zbuf[(size_t)NNODES * DD];  // agg output / next GEMM input
__device__ float  g_als[NNODES * HH];
__device__ float  g_ald[NNODES * HH];
__device__ float  g_pr[(size_t)NNODES * 128];   // scorer P|R per node
__device__ float  g_Wt1[256 * 128];             // W1^T  [256][128]
__device__ float  g_Wt2[256 * 256];             // W2^T  [256][256]
__device__ float  g_Wts[128 * 256];             // [Ws1_top|Ws1_bot]^T [128][256]

// ============================ helpers =======================================
__device__ __forceinline__ uint32_t pack_h2(float a, float b) {
    __half2 h = __floats2half2_rn(a, b);
    return *(uint32_t*)&h;
}

__device__ __forceinline__ void mma16816(float& c0, float& c1, float& c2, float& c3,
                                         uint32_t a0, uint32_t a1, uint32_t a2, uint32_t a3,
                                         uint32_t b0, uint32_t b1) {
    asm volatile(
        "mma.sync.aligned.m16n8k16.row.col.f32.f16.f16.f32 "
        "{%0,%1,%2,%3}, {%4,%5,%6,%7}, {%8,%9}, {%0,%1,%2,%3};"
        : "+f"(c0), "+f"(c1), "+f"(c2), "+f"(c3)
        : "r"(a0), "r"(a1), "r"(a2), "r"(a3), "r"(b0), "r"(b1));
}

// ---------------- init: zero hist + dtype detection --------------------------
__device__ __forceinline__ int check_is_i64(const long long* q) {
    int ok = 1;
#pragma unroll
    for (int i = 0; i < 8; i++) {
        long long v = q[i];
        if (v < 0 || v >= NNODES) ok = 0;
    }
    return ok;
}

__global__ void init_k(const void* ei, const void* eli) {
    int i = blockIdx.x * blockDim.x + threadIdx.x;
    if (i < NNODES) g_fill[i] = 0;
    if (i == 0) {
        g_flag64_e = check_is_i64((const long long*)ei);
        g_flag64_l = check_is_i64((const long long*)eli);
    }
}

// ---------------- edge conversion + self loops + histogram ------------------
__global__ void build_edges(const void* ei) {
    int i = blockIdx.x * blockDim.x + threadIdx.x;
    if (i >= ETOT) return;
    int s, d;
    if (i < NEDGES) {
        if (g_flag64_e) {
            const long long* q = (const long long*)ei;
            s = (int)q[i]; d = (int)q[NEDGES + i];
        } else {
            const int* q = (const int*)ei;
            s = q[i]; d = q[NEDGES + i];
        }
    } else {
        s = i - NEDGES; d = s;   // self loop
    }
    g_esrc[i] = s; g_edst[i] = d;
    atomicAdd(&g_fill[d], 1);
}

__global__ void build_labels(const void* eli) {
    int i = blockIdx.x * blockDim.x + threadIdx.x;
    if (i >= NLBL) return;
    if (g_flag64_l) {
        const long long* q = (const long long*)eli;
        g_lu[i] = (int)q[i]; g_lv[i] = (int)q[NLBL + i];
    } else {
        const int* q = (const int*)eli;
        g_lu[i] = q[i]; g_lv[i] = q[NLBL + i];
    }
}

// ---------------- CSR build: hierarchical scan -------------------------------
__global__ void scan1_k() {
    __shared__ int sh[256];
    int t = threadIdx.x;
    int i = blockIdx.x * 256 + t;
    int v = (i < NNODES) ? g_fill[i] : 0;
    sh[t] = v; __syncthreads();
    for (int o = 1; o < 256; o <<= 1) {
        int a = (t >= o) ? sh[t - o] : 0;
        __syncthreads();
        sh[t] += a;
        __syncthreads();
    }
    if (i < NNODES) g_incl[i] = sh[t];
    if (t == 255) g_bsum[blockIdx.x] = sh[255];
}

__global__ void scan2_k(int nb) {
    __shared__ int sh[256];
    int t = threadIdx.x;
    int v = (t < nb) ? g_bsum[t] : 0;
    sh[t] = v; __syncthreads();
    for (int o = 1; o < 256; o <<= 1) {
        int a = (t >= o) ? sh[t - o] : 0;
        __syncthreads();
        sh[t] += a;
        __syncthreads();
    }
    if (t < nb) g_bsum[t] = sh[t] - v;   // exclusive
}

__global__ void scan3_k() {
    int i = blockIdx.x * blockDim.x + threadIdx.x;
    if (i >= NNODES) return;
    int tot = g_bsum[i >> 8] + g_incl[i];
    int orig = g_fill[i];
    g_rowptr[i + 1] = tot;
    g_fill[i] = tot - orig;              // exclusive offsets for scatter
    if (i == 0) g_rowptr[0] = 0;
}

__global__ void scatter_k() {
    int i = blockIdx.x * blockDim.x + threadIdx.x;
    if (i >= ETOT) return;
    int pos = atomicAdd(&g_fill[g_edst[i]], 1);
    g_csr_src[pos] = g_esrc[i];
}

// ---------------- weight prep (all transposes in one kernel) ----------------
__global__ void prep_weights_k(const float* __restrict__ W1,
                               const float* __restrict__ W2,
                               const float* __restrict__ Ws1) {
    int i = blockIdx.x * blockDim.x + threadIdx.x;
    if (i < 256 * 128) {
        int n = i >> 7, k = i & 127;
        g_Wt1[i] = W1[k * 256 + n];
    }
    int j = i - 256 * 128;
    if (j >= 0 && j < 256 * 256) {
        int n = j >> 8, k = j & 255;
        g_Wt2[j] = W2[k * 256 + n];
    }
    int l = i - 256 * 128 - 256 * 256;
    if (l >= 0 && l < 128 * 256) {
        int n = l >> 8, k = l & 255;
        g_Wts[l] = (n < 64) ? Ws1[k * 64 + n] : Ws1[(256 + k) * 64 + (n - 64)];
    }
}

// ---------------- fp16 mma.sync GEMM (m16n8k16) with register prefetch ------
// C[M,NTR] = A[M,KDIM] @ Bt[NTR,KDIM]^T   (fp32 gmem, fp16 operands, fp32 acc)
// Block tile 128x64, 8 warps (4 in M x 2 in N), warp tile 32x32.
// LOGITS: fused head logits (64-col block == one head). OUTH: write half2 C.
template <int KDIM, int NTR, bool LOGITS, bool OUTH>
__global__ void __launch_bounds__(256) gemm_mma(
    const float* __restrict__ A, const float* __restrict__ Bt,
    void* __restrict__ Cv, int M,
    const float* __restrict__ a_src, const float* __restrict__ a_dst,
    float* __restrict__ als, float* __restrict__ ald)
{
    // smem in half2 units; pitch 20 -> fragment reads conflict-free
    __shared__ uint32_t As[128 * 20];
    __shared__ uint32_t Bs[64 * 20];
    __shared__ float red[4][128];

    int tid = threadIdx.x;
    int wid = tid >> 5, lane = tid & 31;
    int warp_m = wid & 3, warp_n = wid >> 2;
    int g = lane >> 2, t = lane & 3;

    int rowBase = blockIdx.y * 128;
    int colBase = blockIdx.x * 64;

    float c[2][4][4];
#pragma unroll
    for (int i = 0; i < 2; i++)
#pragma unroll
        for (int j = 0; j < 4; j++)
#pragma unroll
            for (int k = 0; k < 4; k++) c[i][j][k] = 0.f;

    constexpr int NC = KDIM / 32;
    float4 ra[4], rb[2];
    {
#pragma unroll
        for (int j = 0; j < 4; j++) {
            int idx = tid + 256 * j;
            int r = idx >> 3, q = idx & 7;
            int gr = rowBase + r;
            ra[j] = (gr < M) ? *(const float4*)(A + (size_t)gr * KDIM + q * 4)
                             : make_float4(0.f, 0.f, 0.f, 0.f);
        }
#pragma unroll
        for (int j = 0; j < 2; j++) {
            int idx = tid + 256 * j;
            int r = idx >> 3, q = idx & 7;
            rb[j] = *(const float4*)(Bt + (size_t)(colBase + r) * KDIM + q * 4);
        }
    }

    for (int kc = 0; kc < NC; kc++) {
        // store prefetched regs (converted to half2) to smem
#pragma unroll
        for (int j = 0; j < 4; j++) {
            int idx = tid + 256 * j;
            int r = idx >> 3, q = idx & 7;
            uint2 u = { pack_h2(ra[j].x, ra[j].y), pack_h2(ra[j].z, ra[j].w) };
            *(uint2*)&As[r * 20 + q * 2] = u;
        }
#pragma unroll
        for (int j = 0; j < 2; j++) {
            int idx = tid + 256 * j;
            int r = idx >> 3, q = idx & 7;
            uint2 u = { pack_h2(rb[j].x, rb[j].y), pack_h2(rb[j].z, rb[j].w) };
            *(uint2*)&Bs[r * 20 + q * 2] = u;
        }
        __syncthreads();

        if (kc + 1 < NC) {
            int k0 = (kc + 1) * 32;
#pragma unroll
            for (int j = 0; j < 4; j++) {
                int idx = tid + 256 * j;
                int r = idx >> 3, q = idx & 7;
                int gr = rowBase + r;
                ra[j] = (gr < M) ? *(const float4*)(A + (size_t)gr * KDIM + k0 + q * 4)
                                 : make_float4(0.f, 0.f, 0.f, 0.f);
            }
#pragma unroll
            for (int j = 0; j < 2; j++) {
                int idx = tid + 256 * j;
                int r = idx >> 3, q = idx & 7;
                rb[j] = *(const float4*)(Bt + (size_t)(colBase + r) * KDIM + k0 + q * 4);
            }
        }

        // two k16 steps per 32-float chunk
#pragma unroll
        for (int ks = 0; ks < 2; ks++) {
            int kk = ks * 8;   // half2 offset
            uint32_t a[2][4];
#pragma unroll
            for (int tm = 0; tm < 2; tm++) {
                int r0 = warp_m * 32 + tm * 16;
                a[tm][0] = As[(r0 + g) * 20 + kk + t];
                a[tm][1] = As[(r0 + g + 8) * 20 + kk + t];
                a[tm][2] = As[(r0 + g) * 20 + kk + t + 4];
                a[tm][3] = As[(r0 + g + 8) * 20 + kk + t + 4];
            }
            uint32_t b[4][2];
#pragma unroll
            for (int tn = 0; tn < 4; tn++) {
                int n0 = warp_n * 32 + tn * 8 + g;
                b[tn][0] = Bs[n0 * 20 + kk + t];
                b[tn][1] = Bs[n0 * 20 + kk + t + 4];
            }
#pragma unroll
            for (int tm = 0; tm < 2; tm++)
#pragma unroll
                for (int tn = 0; tn < 4; tn++)
                    mma16816(c[tm][tn][0], c[tm][tn][1], c[tm][tn][2], c[tm][tn][3],
                             a[tm][0], a[tm][1], a[tm][2], a[tm][3],
                             b[tn][0], b[tn][1]);
        }
        __syncthreads();
    }

    // epilogue: store C (+ fused logits)
    float ps[2][2], pd[2][2];
    if (LOGITS) {
#pragma unroll
        for (int tm = 0; tm < 2; tm++)
            ps[tm][0] = ps[tm][1] = pd[tm][0] = pd[tm][1] = 0.f;
    }
#pragma unroll
    for (int tm = 0; tm < 2; tm++) {
        int r0 = rowBase + warp_m * 32 + tm * 16 + g;
        int r1 = r0 + 8;
#pragma unroll
        for (int tn = 0; tn < 4; tn++) {
            int col = colBase + warp_n * 32 + tn * 8 + t * 2;
            if (LOGITS) {
                float s0 = a_src[col], s1 = a_src[col + 1];
                float d0 = a_dst[col], d1 = a_dst[col + 1];
                ps[tm][0] += c[tm][tn][0] * s0 + c[tm][tn][1] * s1;
                pd[tm][0] += c[tm][tn][0] * d0 + c[tm][tn][1] * d1;
                ps[tm][1] += c[tm][tn][2] * s0 + c[tm][tn][3] * s1;
                pd[tm][1] += c[tm][tn][2] * d0 + c[tm][tn][3] * d1;
            }
            if (OUTH) {
                __half* C = (__half*)Cv;
                if (r0 < M)
                    *(__half2*)(C + (size_t)r0 * NTR + col) =
                        __floats2half2_rn(c[tm][tn][0], c[tm][tn][1]);
                if (r1 < M)
                    *(__half2*)(C + (size_t)r1 * NTR + col) =
                        __floats2half2_rn(c[tm][tn][2], c[tm][tn][3]);
            } else {
                float* C = (float*)Cv;
                if (r0 < M)
                    *(float2*)(C + (size_t)r0 * NTR + col) = make_float2(c[tm][tn][0], c[tm][tn][1]);
                if (r1 < M)
                    *(float2*)(C + (size_t)r1 * NTR + col) = make_float2(c[tm][tn][2], c[tm][tn][3]);
            }
        }
    }
    if (LOGITS) {
#pragma unroll
        for (int tm = 0; tm < 2; tm++)
#pragma unroll
            for (int rr = 0; rr < 2; rr++) {
#pragma unroll
                for (int o = 1; o < 4; o <<= 1) {
                    ps[tm][rr] += __shfl_xor_sync(0xffffffffu, ps[tm][rr], o);
                    pd[tm][rr] += __shfl_xor_sync(0xffffffffu, pd[tm][rr], o);
                }
            }
        __syncthreads();
        if (t == 0) {
#pragma unroll
            for (int tm = 0; tm < 2; tm++) {
                int rl = warp_m * 32 + tm * 16 + g;
                red[warp_n * 2 + 0][rl]     = ps[tm][0];
                red[warp_n * 2 + 0][rl + 8] = ps[tm][1];
                red[warp_n * 2 + 1][rl]     = pd[tm][0];
                red[warp_n * 2 + 1][rl + 8] = pd[tm][1];
            }
        }
        __syncthreads();
        if (tid < 128) {
            int row = rowBase + tid;
            if (row < M) {
                int h = blockIdx.x;   // 64-col block == one head
                als[row * 4 + h] = red[0][tid] + red[2][tid];
                ald[row * 4 + h] = red[1][tid] + red[3][tid];
            }
        }
    }
}

// ---------------- fused softmax + aggregation + bias + ELU ------------------
// warp per node; lane owns 8 channels, head hh = lane>>3.
// p = exp(leaky(als[src]+ald[n])) computed inline (no max: logits are O(1));
// unnormalized accumulate, single scale by 1/sum at the end.
__global__ void __launch_bounds__(256) aggregate_k(const float* __restrict__ bias) {
    int warp = threadIdx.x >> 5, lane = threadIdx.x & 31;
    int n = blockIdx.x * 8 + warp;
    if (n >= NNODES) return;
    int hh = lane >> 3;                         // 8 channels per lane -> head
    int beg = g_rowptr[n], end = g_rowptr[n + 1];
    const __half* hb = g_hbuf;
    float aldn = g_ald[n * 4 + hh];

    float acc[8] = {};
    float psum = 0.f;
#pragma unroll 2
    for (int k = beg; k < end; k++) {
        int s = g_csr_src[k];
        float e = g_als[s * 4 + hh] + aldn;     // one 16B sector per warp
        float v = e > 0.f ? e : 0.2f * e;
        float w = __expf(v);
        psum += w;
        uint4 u = *(const uint4*)(hb + (size_t)s * 256 + lane * 8);
        const __half2* ph = (const __half2*)&u;
#pragma unroll
        for (int j = 0; j < 4; j++) {
            float2 f = __half22float2(ph[j]);
            acc[2 * j]     = fmaf(w, f.x, acc[2 * j]);
            acc[2 * j + 1] = fmaf(w, f.y, acc[2 * j + 1]);
        }
    }
    float inv = 1.f / psum;
    float4 b0 = *(const float4*)&bias[lane * 8];
    float4 b1 = *(const float4*)&bias[lane * 8 + 4];
    float o[8];
    o[0] = fmaf(acc[0], inv, b0.x); o[1] = fmaf(acc[1], inv, b0.y);
    o[2] = fmaf(acc[2], inv, b0.z); o[3] = fmaf(acc[3], inv, b0.w);
    o[4] = fmaf(acc[4], inv, b1.x); o[5] = fmaf(acc[5], inv, b1.y);
    o[6] = fmaf(acc[6], inv, b1.z); o[7] = fmaf(acc[7], inv, b1.w);
#pragma unroll
    for (int j = 0; j < 8; j++)
        o[j] = o[j] > 0.f ? o[j] : (__expf(o[j]) - 1.f);
    float* zp = g_zbuf + (size_t)n * 256 + lane * 8;
    *(float4*)zp       = make_float4(o[0], o[1], o[2], o[3]);
    *(float4*)(zp + 4) = make_float4(o[4], o[5], o[6], o[7]);
}

// ---------------- fused scorer: out = relu(P[u]+R[v]+bs1) . Ws2 + bs2 -------
__global__ void score_k(const float* __restrict__ bs1, const float* __restrict__ Ws2,
                        const float* __restrict__ bs2, float* __restrict__ out) {
    int e = (blockIdx.x * blockDim.x + threadIdx.x) >> 5;
    int lane = threadIdx.x & 31;
    if (e >= NLBL) return;
    int u = g_lu[e], v = g_lv[e];
    const float* pu = g_pr + (size_t)u * 128;
    const float* rv = g_pr + (size_t)v * 128 + 64;
    float s = 0.f;
#pragma unroll
    for (int j = 0; j < 2; j++) {
        int c = lane + j * 32;
        float h = pu[c] + rv[c] + bs1[c];
        h = fmaxf(h, 0.f);
        s = fmaf(h, Ws2[c], s);
    }
#pragma unroll
    for (int o = 16; o; o >>= 1) s += __shfl_xor_sync(0xffffffffu, s, o);
    if (!lane) out[e] = s + bs2[0];
}

// ---------------- launcher --------------------------------------------------
extern "C" void kernel_launch(void* const* d_in, const int* in_sizes, int n_in,
                              void* d_out, int out_size) {
    const float* x   = (const float*)d_in[0];
    const void*  ei  = d_in[1];
    const void*  eli = d_in[2];
    const float* W1  = (const float*)d_in[3];
    const float* as1 = (const float*)d_in[4];
    const float* ad1 = (const float*)d_in[5];
    const float* b1  = (const float*)d_in[6];
    const float* W2  = (const float*)d_in[7];
    const float* as2 = (const float*)d_in[8];
    const float* ad2 = (const float*)d_in[9];
    const float* b2  = (const float*)d_in[10];
    const float* Ws1 = (const float*)d_in[11];
    const float* bs1 = (const float*)d_in[12];
    const float* Ws2 = (const float*)d_in[13];
    const float* bs2 = (const float*)d_in[14];
    float* out = (float*)d_out;

    void *hptr;
    float *zptr, *prptr, *wt1, *wt2, *wts, *alsp, *aldp;
    cudaGetSymbolAddress(&hptr, g_hbuf);
    cudaGetSymbolAddress((void**)&zptr, g_zbuf);
    cudaGetSymbolAddress((void**)&prptr, g_pr);
    cudaGetSymbolAddress((void**)&wt1, g_Wt1);
    cudaGetSymbolAddress((void**)&wt2, g_Wt2);
    cudaGetSymbolAddress((void**)&wts, g_Wts);
    cudaGetSymbolAddress((void**)&alsp, g_als);
    cudaGetSymbolAddress((void**)&aldp, g_ald);

    // side stream + fork/join events (created once, on the non-capture
    // correctness call; host-side only, no device memory involved)
    static cudaStream_t s2 = nullptr;
    static cudaEvent_t evFork = nullptr, evJoin = nullptr;
    if (!s2) {
        cudaStreamCreateWithFlags(&s2, cudaStreamNonBlocking);
        cudaEventCreateWithFlags(&evFork, cudaEventDisableTiming);
        cudaEventCreateWithFlags(&evJoin, cudaEventDisableTiming);
    }

    // fork: CSR build chain on s2, concurrent with weight prep + GEMM1
    cudaEventRecord(evFork, 0);
    cudaStreamWaitEvent(s2, evFork, 0);

    init_k<<<(NNODES + 255) / 256, 256, 0, s2>>>(ei, eli);
    build_edges<<<(ETOT + 255) / 256, 256, 0, s2>>>(ei);
    build_labels<<<(NLBL + 255) / 256, 256, 0, s2>>>(eli);
    int nb = (NNODES + 255) / 256;   // 196
    scan1_k<<<nb, 256, 0, s2>>>();
    scan2_k<<<1, 256, 0, s2>>>(nb);
    scan3_k<<<(NNODES + 255) / 256, 256, 0, s2>>>();
    scatter_k<<<(ETOT + 255) / 256, 256, 0, s2>>>();
    cudaEventRecord(evJoin, s2);

    // main stream: weight prep + layer-1 GEMM (independent of CSR)
    int wtot = 256 * 128 + 256 * 256 + 128 * 256;
    prep_weights_k<<<(wtot + 255) / 256, 256>>>(W1, W2, Ws1);

    int mrows = (NNODES + 127) / 128;   // 391
    gemm_mma<128, 256, true, true><<<dim3(4, mrows), 256>>>(x, wt1, hptr, NNODES,
                                                            as1, ad1, alsp, aldp);

    // join: aggregation needs both CSR and logits
    cudaStreamWaitEvent(0, evJoin, 0);

    // ---- layer 1 edge pipeline (softmax fused into aggregation) ----
    aggregate_k<<<(NNODES + 7) / 8, 256>>>(b1);

    // ---- layer 2 ----
    gemm_mma<256, 256, true, true><<<dim3(4, mrows), 256>>>(zptr, wt2, hptr, NNODES,
                                                            as2, ad2, alsp, aldp);
    aggregate_k<<<(NNODES + 7) / 8, 256>>>(b2);

    // ---- scorer ----
    gemm_mma<256, 128, false, false><<<dim3(2, mrows), 256>>>(zptr, wts, prptr, NNODES,
                                                              nullptr, nullptr, nullptr, nullptr);
    score_k<<<(NLBL + 7) / 8, 256>>>(bs1, Ws2, bs2, out);
}